// round 7
// baseline (speedup 1.0000x reference)
#include <cuda_runtime.h>
#include <cuda_bf16.h>
#include <math.h>

#define BB 16384
#define LL 32

typedef unsigned long long ull;

// scratch (no allocation allowed)
__device__ float g_z[BB * 8];
__device__ float g_T10[BB];

__device__ __forceinline__ ull pack2(float lo, float hi) {
    ull r; asm("mov.b64 %0,{%1,%2};" : "=l"(r) : "f"(lo), "f"(hi)); return r;
}
__device__ __forceinline__ void unpack2(ull v, float& lo, float& hi) {
    asm("mov.b64 {%0,%1},%2;" : "=f"(lo), "=f"(hi) : "l"(v));
}
__device__ __forceinline__ ull fma2(ull a, ull b, ull c) {
    ull d; asm("fma.rn.f32x2 %0,%1,%2,%3;" : "=l"(d) : "l"(a), "l"(b), "l"(c)); return d;
}
__device__ __forceinline__ ull add2(ull a, ull b) {
    ull d; asm("add.rn.f32x2 %0,%1,%2;" : "=l"(d) : "l"(a), "l"(b)); return d;
}

__device__ __forceinline__ float tanh_fast(float x) {
    float e = __expf(2.0f * x);
    return 1.0f - __fdividef(2.0f, e + 1.0f);
}

__device__ __forceinline__ float2 dxval(float s, float2 x0, float2 x1, float2 m0, float2 m1) {
    float s2 = s * s;
    float cx0 = 6.f * s2 - 6.f * s;
    float cm0 = 3.f * s2 - 4.f * s + 1.f;
    float cx1 = -6.f * s2 + 6.f * s;
    float cm1 = 3.f * s2 - 2.f * s;
    float2 r;
    r.x = cx0 * x0.x + cm0 * m0.x + cx1 * x1.x + cm1 * m1.x;
    r.y = cx0 * x0.y + cm0 * m0.y + cx1 * x1.y + cm1 * m1.y;
    return r;
}

// F(s,z) for TWO rows per 4-lane group (g = lane&3 splits k stride-4).
// W2T chunk-XOR swizzle makes the 4 parity groups' LDS.128 conflict-free.
// 4-lane reduce = role-splitting butterfly (even lanes end with row A sums,
// odd with row B); tanh split by row parity; k re-broadcast by 64-bit shfl.
__device__ __forceinline__ void Feval2(const ull* zA, const ull* zB,
                                       float2 dA, float2 dB,
                                       const float* sW1, const float* sW2T,
                                       const ull* sB1p, const float* sB2,
                                       int g, int xo0, int xo1, int xo2, int xo3,
                                       ull* kA, ull* kB) {
    ull aA[8], aB[8];
#pragma unroll
    for (int j = 0; j < 8; j++) { aA[j] = 0ull; aB[j] = 0ull; }

#pragma unroll 2
    for (int kk = g; kk < 256; kk += 4) {
        ulonglong2 w1a = *reinterpret_cast<const ulonglong2*>(sW1 + kk * 8);
        ulonglong2 w1b = *reinterpret_cast<const ulonglong2*>(sW1 + kk * 8 + 4);
        ull bk = sB1p[kk];

        ull accA = fma2(w1a.x, zA[0], bk);
        ull accB = fma2(w1a.x, zB[0], bk);
        accA = fma2(w1a.y, zA[1], accA);
        accB = fma2(w1a.y, zB[1], accB);
        accA = fma2(w1b.x, zA[2], accA);
        accB = fma2(w1b.x, zB[2], accB);
        accA = fma2(w1b.y, zA[3], accA);
        accB = fma2(w1b.y, zB[3], accB);
        float alo, ahi, blo, bhi;
        unpack2(accA, alo, ahi);
        unpack2(accB, blo, bhi);
        float hA = fmaxf(alo + ahi, 0.f);
        float hB = fmaxf(blo + bhi, 0.f);
        ull hhA = pack2(hA, hA);
        ull hhB = pack2(hB, hB);

        const float* base = sW2T + kk * 16;
        ulonglong2 c0 = *reinterpret_cast<const ulonglong2*>(base + xo0);
        ulonglong2 c1 = *reinterpret_cast<const ulonglong2*>(base + xo1);
        ulonglong2 c2 = *reinterpret_cast<const ulonglong2*>(base + xo2);
        ulonglong2 c3 = *reinterpret_cast<const ulonglong2*>(base + xo3);
        aA[0] = fma2(c0.x, hhA, aA[0]);  aB[0] = fma2(c0.x, hhB, aB[0]);
        aA[1] = fma2(c0.y, hhA, aA[1]);  aB[1] = fma2(c0.y, hhB, aB[1]);
        aA[2] = fma2(c1.x, hhA, aA[2]);  aB[2] = fma2(c1.x, hhB, aB[2]);
        aA[3] = fma2(c1.y, hhA, aA[3]);  aB[3] = fma2(c1.y, hhB, aB[3]);
        aA[4] = fma2(c2.x, hhA, aA[4]);  aB[4] = fma2(c2.x, hhB, aB[4]);
        aA[5] = fma2(c2.y, hhA, aA[5]);  aB[5] = fma2(c2.y, hhB, aB[5]);
        aA[6] = fma2(c3.x, hhA, aA[6]);  aB[6] = fma2(c3.x, hhB, aB[6]);
        aA[7] = fma2(c3.y, hhA, aA[7]);  aB[7] = fma2(c3.y, hhB, aB[7]);
    }
    float pA[16], pB[16];
#pragma unroll
    for (int j = 0; j < 8; j++) {
        unpack2(aA[j], pA[2 * j], pA[2 * j + 1]);
        unpack2(aB[j], pB[2 * j], pB[2 * j + 1]);
    }

    // role-splitting butterfly reduce over the 4 group lanes:
    // after stage 2, even lanes hold full row-A sums, odd lanes row-B.
    int odd = g & 1;
    float tot[16];
#pragma unroll
    for (int j = 0; j < 16; j++) {
        float v = odd ? pA[j] : pB[j];           // give away other row's partial
        float r = __shfl_xor_sync(0xffffffffu, v, 1);
        float t = odd ? (pB[j] + r) : (pA[j] + r);
        float r2 = __shfl_xor_sync(0xffffffffu, t, 2);
        tot[j] = t + r2;
    }

    float2 dm;
    dm.x = odd ? dB.x : dA.x;
    dm.y = odd ? dB.y : dA.y;

    ull km[4];
#pragma unroll
    for (int hh = 0; hh < 4; hh++) {
        float t0 = tanh_fast(tot[4 * hh]     + sB2[4 * hh]);
        float t1 = tanh_fast(tot[4 * hh + 1] + sB2[4 * hh + 1]);
        float t2 = tanh_fast(tot[4 * hh + 2] + sB2[4 * hh + 2]);
        float t3 = tanh_fast(tot[4 * hh + 3] + sB2[4 * hh + 3]);
        km[hh] = pack2(t0 * dm.x + t1 * dm.y, t2 * dm.x + t3 * dm.y);
    }
    // exchange with xor-1 partner; select into kA/kB (all lanes end with both)
#pragma unroll
    for (int hh = 0; hh < 4; hh++) {
        ull ko = __shfl_xor_sync(0xffffffffu, km[hh], 1);
        kA[hh] = odd ? ko : km[hh];
        kB[hh] = odd ? km[hh] : ko;
    }
}

__device__ __forceinline__ void substep2(ull* zA, ull* zB,
                                         float2 xaA, float2 xbA, float2 m0A, float2 m1A,
                                         float2 xaB, float2 xbB, float2 m0B, float2 m1B,
                                         float s0,
                                         const float* sW1, const float* sW2T,
                                         const ull* sB1p, const float* sB2,
                                         int g, int xo0, int xo1, int xo2, int xo3) {
    float2 dA1 = dxval(s0,         xaA, xbA, m0A, m1A);
    float2 dA2 = dxval(s0 + 0.25f, xaA, xbA, m0A, m1A);
    float2 dA3 = dxval(s0 + 0.5f,  xaA, xbA, m0A, m1A);
    float2 dB1 = dxval(s0,         xaB, xbB, m0B, m1B);
    float2 dB2 = dxval(s0 + 0.25f, xaB, xbB, m0B, m1B);
    float2 dB3 = dxval(s0 + 0.5f,  xaB, xbB, m0B, m1B);

    const ull C025 = pack2(0.25f, 0.25f);
    const ull C05  = pack2(0.5f, 0.5f);
    const ull C2   = pack2(2.f, 2.f);
    const ull C112 = pack2(1.f / 12.f, 1.f / 12.f);

    ull kcA[4], kcB[4], ksA[4], ksB[4], ztA[4], ztB[4];
    Feval2(zA, zB, dA1, dB1, sW1, sW2T, sB1p, sB2, g, xo0, xo1, xo2, xo3, kcA, kcB);
#pragma unroll
    for (int j = 0; j < 4; j++) {
        ksA[j] = kcA[j]; ztA[j] = fma2(C025, kcA[j], zA[j]);
        ksB[j] = kcB[j]; ztB[j] = fma2(C025, kcB[j], zB[j]);
    }
    Feval2(ztA, ztB, dA2, dB2, sW1, sW2T, sB1p, sB2, g, xo0, xo1, xo2, xo3, kcA, kcB);
#pragma unroll
    for (int j = 0; j < 4; j++) {
        ksA[j] = fma2(C2, kcA[j], ksA[j]); ztA[j] = fma2(C025, kcA[j], zA[j]);
        ksB[j] = fma2(C2, kcB[j], ksB[j]); ztB[j] = fma2(C025, kcB[j], zB[j]);
    }
    Feval2(ztA, ztB, dA2, dB2, sW1, sW2T, sB1p, sB2, g, xo0, xo1, xo2, xo3, kcA, kcB);
#pragma unroll
    for (int j = 0; j < 4; j++) {
        ksA[j] = fma2(C2, kcA[j], ksA[j]); ztA[j] = fma2(C05, kcA[j], zA[j]);
        ksB[j] = fma2(C2, kcB[j], ksB[j]); ztB[j] = fma2(C05, kcB[j], zB[j]);
    }
    Feval2(ztA, ztB, dA3, dB3, sW1, sW2T, sB1p, sB2, g, xo0, xo1, xo2, xo3, kcA, kcB);
#pragma unroll
    for (int j = 0; j < 4; j++) {
        zA[j] = fma2(C112, add2(ksA[j], kcA[j]), zA[j]);
        zB[j] = fma2(C112, add2(ksB[j], kcB[j]), zB[j]);
    }
}

__global__ void __launch_bounds__(32, 8)
k1_ode(const float* __restrict__ X_in, const float* __restrict__ fa_in,
       const int* __restrict__ fa_len,
       const float* __restrict__ W_init, const float* __restrict__ b_init,
       const float* __restrict__ W1, const float* __restrict__ b1,
       const float* __restrict__ W2, const float* __restrict__ b2) {
    __shared__ __align__(16) float sW1[256 * 8];
    __shared__ __align__(16) float sW2T[256 * 16];
    __shared__ __align__(16) ull   sB1p[256];   // (b1, 0) packed
    __shared__ float sB2[16];
    __shared__ float sWI[16];
    __shared__ float sBI[8];
    __shared__ float2 sX[16][33];

    int tid = threadIdx.x;   // 0..31
    for (int i = tid; i < 256 * 8; i += 32) sW1[i] = W1[i];
    // W2 is (16,256); store transposed [k][.] with chunk-XOR swizzle:
    // logical chunk c = j>>2 stored at position (c ^ (k&3)) within row k.
    for (int i = tid; i < 16 * 256; i += 32) {
        int j = i >> 8;    // 0..15
        int k = i & 255;   // 0..255
        int pos = (j >> 2) ^ (k & 3);
        sW2T[k * 16 + pos * 4 + (j & 3)] = W2[i];
    }
    for (int i = tid; i < 256; i += 32) sB1p[i] = pack2(b1[i], 0.f);
    if (tid < 16) sB2[tid] = b2[tid];
    if (tid < 16) sWI[tid] = W_init[tid];
    if (tid < 8)  sBI[tid] = b_init[tid];

    int g = tid & 3;             // k-parity (stride 4)
    int grp = tid >> 2;          // group, 0..7
    int rowA = blockIdx.x * 16 + grp;
    int rowB = rowA + 8;
    // swizzled read offsets: logical chunk c lives at position c^g (16B units)
    int xo0 = ((0 ^ g) * 4), xo1 = ((1 ^ g) * 4), xo2 = ((2 ^ g) * 4), xo3 = ((3 ^ g) * 4);

    // prologue for both rows: mean, normalize, push-zeros-as-shift
#pragma unroll
    for (int rr = 0; rr < 2; rr++) {
        int row = rr ? rowB : rowA;
        int rib = rr ? (grp + 8) : grp;
        const float* Xr = X_in + row * LL;
        const float* Fr = fa_in + row * LL;
        int fl = fa_len[row];

        float s = 0.f;
        for (int t = g; t < LL; t += 4) s += Xr[t];
        s += __shfl_xor_sync(0xffffffffu, s, 1);
        s += __shfl_xor_sync(0xffffffffu, s, 2);
        float mean = s / (float)fl;

        int shift = LL - fl;
        int li = 2 * fl - LL - 1;
        float lastX = (li >= 0) ? (Xr[li] / mean) : 0.f;
        float lastF = Fr[fl - 1];

        for (int q = g; q < LL; q += 4) {
            float fa, xx;
            if (q < shift) { fa = lastF; xx = lastX; }
            else           { fa = Fr[q - shift]; xx = Xr[q - shift] / mean; }
            sX[rib][q] = make_float2(fa, xx);
        }
    }
    __syncwarp();

    float2 x0A = sX[grp][0];
    float2 x0B = sX[grp + 8][0];
    ull zA[4], zB[4];
#pragma unroll
    for (int j = 0; j < 4; j++) {
        float a0 = sBI[2 * j]     + sWI[4 * j]     * x0A.x + sWI[4 * j + 1] * x0A.y;
        float a1 = sBI[2 * j + 1] + sWI[4 * j + 2] * x0A.x + sWI[4 * j + 3] * x0A.y;
        zA[j] = pack2(a0, a1);
        float b0 = sBI[2 * j]     + sWI[4 * j]     * x0B.x + sWI[4 * j + 1] * x0B.y;
        float b1v = sBI[2 * j + 1] + sWI[4 * j + 2] * x0B.x + sWI[4 * j + 3] * x0B.y;
        zB[j] = pack2(b0, b1v);
    }

    float2 xaA = x0A, m0A = make_float2(0.f, 0.f), m1A;
    float2 xaB = x0B, m0B = make_float2(0.f, 0.f), m1B;
    for (int i = 0; i < LL - 1; i++) {
        float2 xbA = sX[grp][i + 1];
        float2 xbB = sX[grp + 8][i + 1];
        m1A.x = xbA.x - xaA.x;  m1A.y = xbA.y - xaA.y;
        m1B.x = xbB.x - xaB.x;  m1B.y = xbB.y - xaB.y;
        if (i == 0) { m0A = m1A; m0B = m1B; }
        substep2(zA, zB, xaA, xbA, m0A, m1A, xaB, xbB, m0B, m1B, 0.0f,
                 sW1, sW2T, sB1p, sB2, g, xo0, xo1, xo2, xo3);
        substep2(zA, zB, xaA, xbA, m0A, m1A, xaB, xbB, m0B, m1B, 0.5f,
                 sW1, sW2T, sB1p, sB2, g, xo0, xo1, xo2, xo3);
        m0A = m1A; m0B = m1B;
        xaA = xbA; xaB = xbB;
    }
    // all 4 group lanes hold identical z; lane g writes floats [2g, 2g+1]
    {
        float a0, a1, b0, b1v;
        unpack2(zA[g], a0, a1);
        unpack2(zB[g], b0, b1v);
        g_z[rowA * 8 + 2 * g]     = a0;
        g_z[rowA * 8 + 2 * g + 1] = a1;
        g_z[rowB * 8 + 2 * g]     = b0;
        g_z[rowB * 8 + 2 * g + 1] = b1v;
    }
}

// ---------------- k2: readout MLP with smem-cached Wr2 ----------------
#define K2_W2   0                    // 200*201 floats
#define K2_W1   (200 * 201)          // 1600
#define K2_B1   (K2_W1 + 1600)       // 200
#define K2_B2   (K2_B1 + 200)        // 200
#define K2_W3   (K2_B2 + 200)        // 200
#define K2_H1   (K2_W3 + 200)        // 8 warps * 1600
#define K2_SMEM_FLOATS (K2_H1 + 8 * 1600)
#define K2_SMEM_BYTES  (K2_SMEM_FLOATS * 4)

__global__ void __launch_bounds__(256, 1)
k2_readout(const float* __restrict__ Wr1, const float* __restrict__ br1,
           const float* __restrict__ Wr2, const float* __restrict__ br2,
           const float* __restrict__ Wr3, const float* __restrict__ br3) {
    extern __shared__ __align__(16) float sm[];
    int tid = threadIdx.x;
    int lane = tid & 31;
    int w = tid >> 5;

    for (int i = tid; i < 200 * 200; i += 256)
        sm[K2_W2 + (i / 200) * 201 + (i % 200)] = Wr2[i];
    for (int i = tid; i < 1600; i += 256) sm[K2_W1 + i] = Wr1[i];
    for (int i = tid; i < 200; i += 256) {
        sm[K2_B1 + i] = br1[i];
        sm[K2_B2 + i] = br2[i];
        sm[K2_W3 + i] = Wr3[i];
    }
    __syncthreads();

    float* h1w = sm + K2_H1 + w * 1600;
    float b3 = __ldg(br3);

    for (int pass = 0; pass < 2; pass++) {
        int row0 = blockIdx.x * 128 + w * 16 + pass * 8;

        float z8[8][8];
#pragma unroll
        for (int r = 0; r < 8; r++) {
            const float4* zp = reinterpret_cast<const float4*>(g_z + (row0 + r) * 8);
            float4 u = zp[0], v = zp[1];
            z8[r][0] = u.x; z8[r][1] = u.y; z8[r][2] = u.z; z8[r][3] = u.w;
            z8[r][4] = v.x; z8[r][5] = v.y; z8[r][6] = v.z; z8[r][7] = v.w;
        }
        for (int j = lane; j < 200; j += 32) {
            const float4* wp = reinterpret_cast<const float4*>(sm + K2_W1 + j * 8);
            float4 a = wp[0], b = wp[1];
            float bj = sm[K2_B1 + j];
#pragma unroll
            for (int r = 0; r < 8; r++) {
                float h = bj;
                h = fmaf(a.x, z8[r][0], h); h = fmaf(a.y, z8[r][1], h);
                h = fmaf(a.z, z8[r][2], h); h = fmaf(a.w, z8[r][3], h);
                h = fmaf(b.x, z8[r][4], h); h = fmaf(b.y, z8[r][5], h);
                h = fmaf(b.z, z8[r][6], h); h = fmaf(b.w, z8[r][7], h);
                h1w[j * 8 + r] = h * normcdff(h);
            }
        }
        __syncwarp();

        ull acc[7][4];
#pragma unroll
        for (int u = 0; u < 7; u++)
#pragma unroll
            for (int q = 0; q < 4; q++) acc[u][q] = 0ull;

        for (int q = 0; q < 200; q++) {
            const ull* hp = reinterpret_cast<const ull*>(h1w + q * 8);
            ull h01 = hp[0], h23 = hp[1], h45 = hp[2], h67 = hp[3];
#pragma unroll
            for (int u = 0; u < 7; u++) {
                int j = lane + 32 * u;
                float wv = (j < 200) ? sm[K2_W2 + j * 201 + q] : 0.f;
                ull w2 = pack2(wv, wv);
                acc[u][0] = fma2(w2, h01, acc[u][0]);
                acc[u][1] = fma2(w2, h23, acc[u][1]);
                acc[u][2] = fma2(w2, h45, acc[u][2]);
                acc[u][3] = fma2(w2, h67, acc[u][3]);
            }
        }

        float part[8];
#pragma unroll
        for (int r = 0; r < 8; r++) part[r] = 0.f;
#pragma unroll
        for (int u = 0; u < 7; u++) {
            int j = lane + 32 * u;
            if (j < 200) {
                float w3 = sm[K2_W3 + j];
                float b2j = sm[K2_B2 + j];
#pragma unroll
                for (int q = 0; q < 4; q++) {
                    float v0, v1; unpack2(acc[u][q], v0, v1);
                    v0 += b2j; v1 += b2j;
                    part[2 * q]     = fmaf(w3, v0 * normcdff(v0), part[2 * q]);
                    part[2 * q + 1] = fmaf(w3, v1 * normcdff(v1), part[2 * q + 1]);
                }
            }
        }
#pragma unroll
        for (int r = 0; r < 8; r++)
#pragma unroll
            for (int m = 16; m >= 1; m >>= 1)
                part[r] += __shfl_xor_sync(0xffffffffu, part[r], m);

        if (lane < 8) {
            float t = part[lane] + b3;
            float sg = 1.0f / (1.0f + expf(-t));
            g_T10[row0 + lane] = 0.1f + sg * (7.0f - 0.1f);
        }
        __syncwarp();
    }
}

__global__ void __launch_bounds__(128)
k3_out(const float* __restrict__ fa_in, const float* __restrict__ TR,
       const int* __restrict__ fa_len, float* __restrict__ out) {
    int lane = threadIdx.x & 31;
    int w = threadIdx.x >> 5;
    int row = blockIdx.x * 4 + w;

    float T10 = g_T10[row];
    float R1 = 1.0f / T10;
    float E = expf(-TR[row] * R1);
    float fa = fa_in[row * LL + lane];
    float xo = (1.0f - E) * sinf(fa) / (1.0f - cosf(fa) * E);

    float ssum = xo;
#pragma unroll
    for (int m = 16; m >= 1; m >>= 1) ssum += __shfl_xor_sync(0xffffffffu, ssum, m);

    float fl = (float)fa_len[row];
    out[row * LL + lane] = xo * fl / ssum;
    if (lane == 0) {
        out[BB * LL + row] = T10;       // T10
        out[BB * LL + BB + row] = 1.0f; // M0
    }
}

extern "C" void kernel_launch(void* const* d_in, const int* in_sizes, int n_in,
                              void* d_out, int out_size) {
    const float* X_fa_in    = (const float*)d_in[0];
    const float* fa_vals_in = (const float*)d_in[1];
    const float* TR_vals    = (const float*)d_in[2];
    const float* W_init     = (const float*)d_in[3];
    const float* b_init     = (const float*)d_in[4];
    const float* W1         = (const float*)d_in[5];
    const float* b1         = (const float*)d_in[6];
    const float* W2         = (const float*)d_in[7];
    const float* b2         = (const float*)d_in[8];
    const float* Wr1        = (const float*)d_in[9];
    const float* br1        = (const float*)d_in[10];
    const float* Wr2        = (const float*)d_in[11];
    const float* br2        = (const float*)d_in[12];
    const float* Wr3        = (const float*)d_in[13];
    const float* br3        = (const float*)d_in[14];
    // d_in[15] = fa_mask (unused)
    const int*   fa_len     = (const int*)d_in[16];

    float* out = (float*)d_out;

    // host-state op (not a stream op): capture-safe, deterministic, no alloc
    cudaFuncSetAttribute(k2_readout, cudaFuncAttributeMaxDynamicSharedMemorySize,
                         K2_SMEM_BYTES);

    k1_ode<<<BB / 16, 32>>>(X_fa_in, fa_vals_in, fa_len, W_init, b_init, W1, b1, W2, b2);
    k2_readout<<<128, 256, K2_SMEM_BYTES>>>(Wr1, br1, Wr2, br2, Wr3, br3);
    k3_out<<<BB / 4, 128>>>(fa_vals_in, TR_vals, fa_len, out);
}

// round 8
// speedup vs baseline: 1.1127x; 1.1127x over previous
#include <cuda_runtime.h>
#include <cuda_bf16.h>
#include <math.h>

#define BB 16384
#define LL 32

typedef unsigned long long ull;

// scratch (no allocation allowed)
__device__ float g_z[BB * 8];
__device__ float g_T10[BB];

__device__ __forceinline__ ull pack2(float lo, float hi) {
    ull r; asm("mov.b64 %0,{%1,%2};" : "=l"(r) : "f"(lo), "f"(hi)); return r;
}
__device__ __forceinline__ void unpack2(ull v, float& lo, float& hi) {
    asm("mov.b64 {%0,%1},%2;" : "=f"(lo), "=f"(hi) : "l"(v));
}
__device__ __forceinline__ ull fma2(ull a, ull b, ull c) {
    ull d; asm("fma.rn.f32x2 %0,%1,%2,%3;" : "=l"(d) : "l"(a), "l"(b), "l"(c)); return d;
}
__device__ __forceinline__ ull add2(ull a, ull b) {
    ull d; asm("add.rn.f32x2 %0,%1,%2;" : "=l"(d) : "l"(a), "l"(b)); return d;
}

__device__ __forceinline__ float tanh_fast(float x) {
    float e = __expf(2.0f * x);
    return 1.0f - __fdividef(2.0f, e + 1.0f);
}

__device__ __forceinline__ float2 dxval(float s, float2 x0, float2 x1, float2 m0, float2 m1) {
    float s2 = s * s;
    float cx0 = 6.f * s2 - 6.f * s;
    float cm0 = 3.f * s2 - 4.f * s + 1.f;
    float cx1 = -6.f * s2 + 6.f * s;
    float cm1 = 3.f * s2 - 2.f * s;
    float2 r;
    r.x = cx0 * x0.x + cm0 * m0.x + cx1 * x1.x + cm1 * m1.x;
    r.y = cx0 * x0.y + cm0 * m0.y + cx1 * x1.y + cm1 * m1.y;
    return r;
}

// F(s,z) for TWO rows per lane. Warp splits k two ways:
//  - lane parity g (kk stride 2): the R5/R6-proven 2-address LDS pattern
//  - warp half kh (lanes 0-15: k in [0,128); 16-31: [128,256))
// => 16 rows/warp at 56 LDS-wavefronts/row (R6 rate, R5 concurrency).
// Reduce: xor-16 (combine k-halves) then role-split xor-1 butterfly;
// tanh split by row parity; k re-broadcast via 64-bit shuffles.
__device__ __forceinline__ void Feval2(const ull* zA, const ull* zB,
                                       float2 dA, float2 dB,
                                       const float* sW1, const float* sW2T,
                                       const ull* sB1p, const float* sB2,
                                       int kbeg, int odd, ull* kA, ull* kB) {
    ull aA[8], aB[8];
#pragma unroll
    for (int j = 0; j < 8; j++) { aA[j] = 0ull; aB[j] = 0ull; }

#pragma unroll 2
    for (int t = 0; t < 64; t++) {
        int kk = kbeg + 2 * t;
        ulonglong2 w1a = *reinterpret_cast<const ulonglong2*>(sW1 + kk * 8);
        ulonglong2 w1b = *reinterpret_cast<const ulonglong2*>(sW1 + kk * 8 + 4);
        ull bk = sB1p[kk];

        ull accA = fma2(w1a.x, zA[0], bk);
        ull accB = fma2(w1a.x, zB[0], bk);
        accA = fma2(w1a.y, zA[1], accA);
        accB = fma2(w1a.y, zB[1], accB);
        accA = fma2(w1b.x, zA[2], accA);
        accB = fma2(w1b.x, zB[2], accB);
        accA = fma2(w1b.y, zA[3], accA);
        accB = fma2(w1b.y, zB[3], accB);
        float alo, ahi, blo, bhi;
        unpack2(accA, alo, ahi);
        unpack2(accB, blo, bhi);
        float hA = fmaxf(alo + ahi, 0.f);
        float hB = fmaxf(blo + bhi, 0.f);
        ull hhA = pack2(hA, hA);
        ull hhB = pack2(hB, hB);

        const float* base = sW2T + kk * 16;
        ulonglong2 c0 = *reinterpret_cast<const ulonglong2*>(base);
        ulonglong2 c1 = *reinterpret_cast<const ulonglong2*>(base + 4);
        ulonglong2 c2 = *reinterpret_cast<const ulonglong2*>(base + 8);
        ulonglong2 c3 = *reinterpret_cast<const ulonglong2*>(base + 12);
        aA[0] = fma2(c0.x, hhA, aA[0]);  aB[0] = fma2(c0.x, hhB, aB[0]);
        aA[1] = fma2(c0.y, hhA, aA[1]);  aB[1] = fma2(c0.y, hhB, aB[1]);
        aA[2] = fma2(c1.x, hhA, aA[2]);  aB[2] = fma2(c1.x, hhB, aB[2]);
        aA[3] = fma2(c1.y, hhA, aA[3]);  aB[3] = fma2(c1.y, hhB, aB[3]);
        aA[4] = fma2(c2.x, hhA, aA[4]);  aB[4] = fma2(c2.x, hhB, aB[4]);
        aA[5] = fma2(c2.y, hhA, aA[5]);  aB[5] = fma2(c2.y, hhB, aB[5]);
        aA[6] = fma2(c3.x, hhA, aA[6]);  aB[6] = fma2(c3.x, hhB, aB[6]);
        aA[7] = fma2(c3.y, hhA, aA[7]);  aB[7] = fma2(c3.y, hhB, aB[7]);
    }
    float pA[16], pB[16];
#pragma unroll
    for (int j = 0; j < 8; j++) {
        unpack2(aA[j], pA[2 * j], pA[2 * j + 1]);
        unpack2(aB[j], pB[2 * j], pB[2 * j + 1]);
    }

    // stage 1: combine the two k-halves (xor 16)
#pragma unroll
    for (int j = 0; j < 16; j++) {
        pA[j] += __shfl_xor_sync(0xffffffffu, pA[j], 16);
        pB[j] += __shfl_xor_sync(0xffffffffu, pB[j], 16);
    }
    // stage 2: role-split pair reduce (xor 1): even lane -> row A, odd -> row B
    float tot[16];
#pragma unroll
    for (int j = 0; j < 16; j++) {
        float v = odd ? pA[j] : pB[j];          // give away other row's partial
        float r = __shfl_xor_sync(0xffffffffu, v, 1);
        tot[j] = (odd ? pB[j] : pA[j]) + r;
    }

    float2 dm;
    dm.x = odd ? dB.x : dA.x;
    dm.y = odd ? dB.y : dA.y;

    ull km[4];
#pragma unroll
    for (int hh = 0; hh < 4; hh++) {
        float t0 = tanh_fast(tot[4 * hh]     + sB2[4 * hh]);
        float t1 = tanh_fast(tot[4 * hh + 1] + sB2[4 * hh + 1]);
        float t2 = tanh_fast(tot[4 * hh + 2] + sB2[4 * hh + 2]);
        float t3 = tanh_fast(tot[4 * hh + 3] + sB2[4 * hh + 3]);
        km[hh] = pack2(t0 * dm.x + t1 * dm.y, t2 * dm.x + t3 * dm.y);
    }
    // exchange with xor-1 partner; all lanes end with both rows' k
#pragma unroll
    for (int hh = 0; hh < 4; hh++) {
        ull ko = __shfl_xor_sync(0xffffffffu, km[hh], 1);
        kA[hh] = odd ? ko : km[hh];
        kB[hh] = odd ? km[hh] : ko;
    }
}

__device__ __forceinline__ void substep2(ull* zA, ull* zB,
                                         float2 xaA, float2 xbA, float2 m0A, float2 m1A,
                                         float2 xaB, float2 xbB, float2 m0B, float2 m1B,
                                         float s0,
                                         const float* sW1, const float* sW2T,
                                         const ull* sB1p, const float* sB2,
                                         int kbeg, int odd) {
    float2 dA1 = dxval(s0,         xaA, xbA, m0A, m1A);
    float2 dA2 = dxval(s0 + 0.25f, xaA, xbA, m0A, m1A);
    float2 dA3 = dxval(s0 + 0.5f,  xaA, xbA, m0A, m1A);
    float2 dB1 = dxval(s0,         xaB, xbB, m0B, m1B);
    float2 dB2 = dxval(s0 + 0.25f, xaB, xbB, m0B, m1B);
    float2 dB3 = dxval(s0 + 0.5f,  xaB, xbB, m0B, m1B);

    const ull C025 = pack2(0.25f, 0.25f);
    const ull C05  = pack2(0.5f, 0.5f);
    const ull C2   = pack2(2.f, 2.f);
    const ull C112 = pack2(1.f / 12.f, 1.f / 12.f);

    ull kcA[4], kcB[4], ksA[4], ksB[4], ztA[4], ztB[4];
    Feval2(zA, zB, dA1, dB1, sW1, sW2T, sB1p, sB2, kbeg, odd, kcA, kcB);
#pragma unroll
    for (int j = 0; j < 4; j++) {
        ksA[j] = kcA[j]; ztA[j] = fma2(C025, kcA[j], zA[j]);
        ksB[j] = kcB[j]; ztB[j] = fma2(C025, kcB[j], zB[j]);
    }
    Feval2(ztA, ztB, dA2, dB2, sW1, sW2T, sB1p, sB2, kbeg, odd, kcA, kcB);
#pragma unroll
    for (int j = 0; j < 4; j++) {
        ksA[j] = fma2(C2, kcA[j], ksA[j]); ztA[j] = fma2(C025, kcA[j], zA[j]);
        ksB[j] = fma2(C2, kcB[j], ksB[j]); ztB[j] = fma2(C025, kcB[j], zB[j]);
    }
    Feval2(ztA, ztB, dA2, dB2, sW1, sW2T, sB1p, sB2, kbeg, odd, kcA, kcB);
#pragma unroll
    for (int j = 0; j < 4; j++) {
        ksA[j] = fma2(C2, kcA[j], ksA[j]); ztA[j] = fma2(C05, kcA[j], zA[j]);
        ksB[j] = fma2(C2, kcB[j], ksB[j]); ztB[j] = fma2(C05, kcB[j], zB[j]);
    }
    Feval2(ztA, ztB, dA3, dB3, sW1, sW2T, sB1p, sB2, kbeg, odd, kcA, kcB);
#pragma unroll
    for (int j = 0; j < 4; j++) {
        zA[j] = fma2(C112, add2(ksA[j], kcA[j]), zA[j]);
        zB[j] = fma2(C112, add2(ksB[j], kcB[j]), zB[j]);
    }
}

__global__ void __launch_bounds__(32, 8)
k1_ode(const float* __restrict__ X_in, const float* __restrict__ fa_in,
       const int* __restrict__ fa_len,
       const float* __restrict__ W_init, const float* __restrict__ b_init,
       const float* __restrict__ W1, const float* __restrict__ b1,
       const float* __restrict__ W2, const float* __restrict__ b2) {
    __shared__ __align__(16) float sW1[256 * 8];
    __shared__ __align__(16) float sW2T[256 * 16];
    __shared__ __align__(16) ull   sB1p[256];   // (b1, 0) packed
    __shared__ float sB2[16];
    __shared__ float sWI[16];
    __shared__ float sBI[8];
    __shared__ float2 sX[16][33];

    int tid = threadIdx.x;   // 0..31
    for (int i = tid; i < 256 * 8; i += 32) sW1[i] = W1[i];
    // W2 is (16,256); store transposed [k][j]
    for (int i = tid; i < 16 * 256; i += 32) {
        int j = i >> 8;    // 0..15
        int k = i & 255;   // 0..255
        sW2T[k * 16 + j] = W2[i];
    }
    for (int i = tid; i < 256; i += 32) sB1p[i] = pack2(b1[i], 0.f);
    if (tid < 16) sB2[tid] = b2[tid];
    if (tid < 16) sWI[tid] = W_init[tid];
    if (tid < 8)  sBI[tid] = b_init[tid];

    int g  = tid & 1;            // k-parity within half (stride 2)
    int kh = (tid >> 4) & 1;     // k-half: 0 -> [0,128), 1 -> [128,256)
    int p  = (tid >> 1) & 7;     // pair id, 0..7
    int kbeg = kh * 128 + g;
    int q0 = g + 2 * kh;         // 0..3: this lane's slot among the row's 4 lanes
    int rowA = blockIdx.x * 16 + p;
    int rowB = rowA + 8;

    // prologue for both rows: mean, normalize, push-zeros-as-shift
#pragma unroll
    for (int rr = 0; rr < 2; rr++) {
        int row = rr ? rowB : rowA;
        int rib = rr ? (p + 8) : p;
        const float* Xr = X_in + row * LL;
        const float* Fr = fa_in + row * LL;
        int fl = fa_len[row];

        float s = 0.f;
        for (int t = q0; t < LL; t += 4) s += Xr[t];
        s += __shfl_xor_sync(0xffffffffu, s, 1);
        s += __shfl_xor_sync(0xffffffffu, s, 16);
        float mean = s / (float)fl;

        int shift = LL - fl;
        int li = 2 * fl - LL - 1;
        float lastX = (li >= 0) ? (Xr[li] / mean) : 0.f;
        float lastF = Fr[fl - 1];

        for (int q = q0; q < LL; q += 4) {
            float fa, xx;
            if (q < shift) { fa = lastF; xx = lastX; }
            else           { fa = Fr[q - shift]; xx = Xr[q - shift] / mean; }
            sX[rib][q] = make_float2(fa, xx);
        }
    }
    __syncwarp();

    float2 x0A = sX[p][0];
    float2 x0B = sX[p + 8][0];
    ull zA[4], zB[4];
#pragma unroll
    for (int j = 0; j < 4; j++) {
        float a0 = sBI[2 * j]     + sWI[4 * j]     * x0A.x + sWI[4 * j + 1] * x0A.y;
        float a1 = sBI[2 * j + 1] + sWI[4 * j + 2] * x0A.x + sWI[4 * j + 3] * x0A.y;
        zA[j] = pack2(a0, a1);
        float b0 = sBI[2 * j]     + sWI[4 * j]     * x0B.x + sWI[4 * j + 1] * x0B.y;
        float b1v = sBI[2 * j + 1] + sWI[4 * j + 2] * x0B.x + sWI[4 * j + 3] * x0B.y;
        zB[j] = pack2(b0, b1v);
    }

    float2 xaA = x0A, m0A = make_float2(0.f, 0.f), m1A;
    float2 xaB = x0B, m0B = make_float2(0.f, 0.f), m1B;
    for (int i = 0; i < LL - 1; i++) {
        float2 xbA = sX[p][i + 1];
        float2 xbB = sX[p + 8][i + 1];
        m1A.x = xbA.x - xaA.x;  m1A.y = xbA.y - xaA.y;
        m1B.x = xbB.x - xaB.x;  m1B.y = xbB.y - xaB.y;
        if (i == 0) { m0A = m1A; m0B = m1B; }
        substep2(zA, zB, xaA, xbA, m0A, m1A, xaB, xbB, m0B, m1B, 0.0f,
                 sW1, sW2T, sB1p, sB2, kbeg, g);
        substep2(zA, zB, xaA, xbA, m0A, m1A, xaB, xbB, m0B, m1B, 0.5f,
                 sW1, sW2T, sB1p, sB2, kbeg, g);
        m0A = m1A; m0B = m1B;
        xaA = xbA; xaB = xbB;
    }
    // all 4 lanes of the row hold identical z; lane slot q0 writes [2q0, 2q0+1]
    {
        float a0, a1, b0, b1v;
        unpack2(zA[q0], a0, a1);
        unpack2(zB[q0], b0, b1v);
        g_z[rowA * 8 + 2 * q0]     = a0;
        g_z[rowA * 8 + 2 * q0 + 1] = a1;
        g_z[rowB * 8 + 2 * q0]     = b0;
        g_z[rowB * 8 + 2 * q0 + 1] = b1v;
    }
}

// ---------------- k2: readout MLP with smem-cached Wr2 ----------------
#define K2_W2   0                    // 200*201 floats
#define K2_W1   (200 * 201)          // 1600
#define K2_B1   (K2_W1 + 1600)       // 200
#define K2_B2   (K2_B1 + 200)        // 200
#define K2_W3   (K2_B2 + 200)        // 200
#define K2_H1   (K2_W3 + 200)        // 8 warps * 1600
#define K2_SMEM_FLOATS (K2_H1 + 8 * 1600)
#define K2_SMEM_BYTES  (K2_SMEM_FLOATS * 4)

__global__ void __launch_bounds__(256, 1)
k2_readout(const float* __restrict__ Wr1, const float* __restrict__ br1,
           const float* __restrict__ Wr2, const float* __restrict__ br2,
           const float* __restrict__ Wr3, const float* __restrict__ br3) {
    extern __shared__ __align__(16) float sm[];
    int tid = threadIdx.x;
    int lane = tid & 31;
    int w = tid >> 5;

    for (int i = tid; i < 200 * 200; i += 256)
        sm[K2_W2 + (i / 200) * 201 + (i % 200)] = Wr2[i];
    for (int i = tid; i < 1600; i += 256) sm[K2_W1 + i] = Wr1[i];
    for (int i = tid; i < 200; i += 256) {
        sm[K2_B1 + i] = br1[i];
        sm[K2_B2 + i] = br2[i];
        sm[K2_W3 + i] = Wr3[i];
    }
    __syncthreads();

    float* h1w = sm + K2_H1 + w * 1600;
    float b3 = __ldg(br3);

    for (int pass = 0; pass < 2; pass++) {
        int row0 = blockIdx.x * 128 + w * 16 + pass * 8;

        float z8[8][8];
#pragma unroll
        for (int r = 0; r < 8; r++) {
            const float4* zp = reinterpret_cast<const float4*>(g_z + (row0 + r) * 8);
            float4 u = zp[0], v = zp[1];
            z8[r][0] = u.x; z8[r][1] = u.y; z8[r][2] = u.z; z8[r][3] = u.w;
            z8[r][4] = v.x; z8[r][5] = v.y; z8[r][6] = v.z; z8[r][7] = v.w;
        }
        for (int j = lane; j < 200; j += 32) {
            const float4* wp = reinterpret_cast<const float4*>(sm + K2_W1 + j * 8);
            float4 a = wp[0], b = wp[1];
            float bj = sm[K2_B1 + j];
#pragma unroll
            for (int r = 0; r < 8; r++) {
                float h = bj;
                h = fmaf(a.x, z8[r][0], h); h = fmaf(a.y, z8[r][1], h);
                h = fmaf(a.z, z8[r][2], h); h = fmaf(a.w, z8[r][3], h);
                h = fmaf(b.x, z8[r][4], h); h = fmaf(b.y, z8[r][5], h);
                h = fmaf(b.z, z8[r][6], h); h = fmaf(b.w, z8[r][7], h);
                h1w[j * 8 + r] = h * normcdff(h);
            }
        }
        __syncwarp();

        ull acc[7][4];
#pragma unroll
        for (int u = 0; u < 7; u++)
#pragma unroll
            for (int q = 0; q < 4; q++) acc[u][q] = 0ull;

        for (int q = 0; q < 200; q++) {
            const ull* hp = reinterpret_cast<const ull*>(h1w + q * 8);
            ull h01 = hp[0], h23 = hp[1], h45 = hp[2], h67 = hp[3];
#pragma unroll
            for (int u = 0; u < 7; u++) {
                int j = lane + 32 * u;
                float wv = (j < 200) ? sm[K2_W2 + j * 201 + q] : 0.f;
                ull w2 = pack2(wv, wv);
                acc[u][0] = fma2(w2, h01, acc[u][0]);
                acc[u][1] = fma2(w2, h23, acc[u][1]);
                acc[u][2] = fma2(w2, h45, acc[u][2]);
                acc[u][3] = fma2(w2, h67, acc[u][3]);
            }
        }

        float part[8];
#pragma unroll
        for (int r = 0; r < 8; r++) part[r] = 0.f;
#pragma unroll
        for (int u = 0; u < 7; u++) {
            int j = lane + 32 * u;
            if (j < 200) {
                float w3 = sm[K2_W3 + j];
                float b2j = sm[K2_B2 + j];
#pragma unroll
                for (int q = 0; q < 4; q++) {
                    float v0, v1; unpack2(acc[u][q], v0, v1);
                    v0 += b2j; v1 += b2j;
                    part[2 * q]     = fmaf(w3, v0 * normcdff(v0), part[2 * q]);
                    part[2 * q + 1] = fmaf(w3, v1 * normcdff(v1), part[2 * q + 1]);
                }
            }
        }
#pragma unroll
        for (int r = 0; r < 8; r++)
#pragma unroll
            for (int m = 16; m >= 1; m >>= 1)
                part[r] += __shfl_xor_sync(0xffffffffu, part[r], m);

        if (lane < 8) {
            float t = part[lane] + b3;
            float sg = 1.0f / (1.0f + expf(-t));
            g_T10[row0 + lane] = 0.1f + sg * (7.0f - 0.1f);
        }
        __syncwarp();
    }
}

__global__ void __launch_bounds__(128)
k3_out(const float* __restrict__ fa_in, const float* __restrict__ TR,
       const int* __restrict__ fa_len, float* __restrict__ out) {
    int lane = threadIdx.x & 31;
    int w = threadIdx.x >> 5;
    int row = blockIdx.x * 4 + w;

    float T10 = g_T10[row];
    float R1 = 1.0f / T10;
    float E = expf(-TR[row] * R1);
    float fa = fa_in[row * LL + lane];
    float xo = (1.0f - E) * sinf(fa) / (1.0f - cosf(fa) * E);

    float ssum = xo;
#pragma unroll
    for (int m = 16; m >= 1; m >>= 1) ssum += __shfl_xor_sync(0xffffffffu, ssum, m);

    float fl = (float)fa_len[row];
    out[row * LL + lane] = xo * fl / ssum;
    if (lane == 0) {
        out[BB * LL + row] = T10;       // T10
        out[BB * LL + BB + row] = 1.0f; // M0
    }
}

extern "C" void kernel_launch(void* const* d_in, const int* in_sizes, int n_in,
                              void* d_out, int out_size) {
    const float* X_fa_in    = (const float*)d_in[0];
    const float* fa_vals_in = (const float*)d_in[1];
    const float* TR_vals    = (const float*)d_in[2];
    const float* W_init     = (const float*)d_in[3];
    const float* b_init     = (const float*)d_in[4];
    const float* W1         = (const float*)d_in[5];
    const float* b1         = (const float*)d_in[6];
    const float* W2         = (const float*)d_in[7];
    const float* b2         = (const float*)d_in[8];
    const float* Wr1        = (const float*)d_in[9];
    const float* br1        = (const float*)d_in[10];
    const float* Wr2        = (const float*)d_in[11];
    const float* br2        = (const float*)d_in[12];
    const float* Wr3        = (const float*)d_in[13];
    const float* br3        = (const float*)d_in[14];
    // d_in[15] = fa_mask (unused)
    const int*   fa_len     = (const int*)d_in[16];

    float* out = (float*)d_out;

    // host-state op (not a stream op): capture-safe, deterministic, no alloc
    cudaFuncSetAttribute(k2_readout, cudaFuncAttributeMaxDynamicSharedMemorySize,
                         K2_SMEM_BYTES);

    k1_ode<<<BB / 16, 32>>>(X_fa_in, fa_vals_in, fa_len, W_init, b_init, W1, b1, W2, b2);
    k2_readout<<<128, 256, K2_SMEM_BYTES>>>(Wr1, br1, Wr2, br2, Wr3, br3);
    k3_out<<<BB / 4, 128>>>(fa_vals_in, TR_vals, fa_len, out);
}

// round 9
// speedup vs baseline: 1.1890x; 1.0685x over previous
#include <cuda_runtime.h>
#include <cuda_bf16.h>
#include <math.h>

#define BB 16384
#define LL 32

typedef unsigned long long ull;

// scratch (no allocation allowed)
__device__ float g_z[BB * 8];
__device__ float g_T10[BB];

__device__ __forceinline__ ull pack2(float lo, float hi) {
    ull r; asm("mov.b64 %0,{%1,%2};" : "=l"(r) : "f"(lo), "f"(hi)); return r;
}
__device__ __forceinline__ void unpack2(ull v, float& lo, float& hi) {
    asm("mov.b64 {%0,%1},%2;" : "=f"(lo), "=f"(hi) : "l"(v));
}
__device__ __forceinline__ ull fma2(ull a, ull b, ull c) {
    ull d; asm("fma.rn.f32x2 %0,%1,%2,%3;" : "=l"(d) : "l"(a), "l"(b), "l"(c)); return d;
}
__device__ __forceinline__ ull add2(ull a, ull b) {
    ull d; asm("add.rn.f32x2 %0,%1,%2;" : "=l"(d) : "l"(a), "l"(b)); return d;
}

__device__ __forceinline__ float tanh_fast(float x) {
    float e = __expf(2.0f * x);
    return 1.0f - __fdividef(2.0f, e + 1.0f);
}

__device__ __forceinline__ float2 dxval(float s, float2 x0, float2 x1, float2 m0, float2 m1) {
    float s2 = s * s;
    float cx0 = 6.f * s2 - 6.f * s;
    float cm0 = 3.f * s2 - 4.f * s + 1.f;
    float cx1 = -6.f * s2 + 6.f * s;
    float cm1 = 3.f * s2 - 2.f * s;
    float2 r;
    r.x = cx0 * x0.x + cm0 * m0.x + cx1 * x1.x + cm1 * m1.x;
    r.y = cx0 * x0.y + cm0 * m0.y + cx1 * x1.y + cm1 * m1.y;
    return r;
}

// F(s,z) for TWO rows per lane. Warp splits k two ways:
//  - lane parity g (kk stride 2)
//  - warp half kh (lanes 0-15: k in [0,128); 16-31: [128,256))
// Reduce: xor-1 role-split (even lane -> row A, odd -> row B), then xor-16
// to combine k-halves. tanh epilogue split across kh (8 tanh/lane), results
// exchanged via xor-16; k re-broadcast across xor-1.
__device__ __forceinline__ void Feval2(const ull* zA, const ull* zB,
                                       float2 dA, float2 dB,
                                       const float* sW1, const float* sW2T,
                                       const ull* sB1p, const float* sB2,
                                       int kbeg, int odd, int kh,
                                       ull* kA, ull* kB) {
    ull aA[8], aB[8];
#pragma unroll
    for (int j = 0; j < 8; j++) { aA[j] = 0ull; aB[j] = 0ull; }

#pragma unroll 4
    for (int t = 0; t < 64; t++) {
        int kk = kbeg + 2 * t;
        ulonglong2 w1a = *reinterpret_cast<const ulonglong2*>(sW1 + kk * 8);
        ulonglong2 w1b = *reinterpret_cast<const ulonglong2*>(sW1 + kk * 8 + 4);
        ull bk = sB1p[kk];

        ull accA = fma2(w1a.x, zA[0], bk);
        ull accB = fma2(w1a.x, zB[0], bk);
        accA = fma2(w1a.y, zA[1], accA);
        accB = fma2(w1a.y, zB[1], accB);
        accA = fma2(w1b.x, zA[2], accA);
        accB = fma2(w1b.x, zB[2], accB);
        accA = fma2(w1b.y, zA[3], accA);
        accB = fma2(w1b.y, zB[3], accB);
        float alo, ahi, blo, bhi;
        unpack2(accA, alo, ahi);
        unpack2(accB, blo, bhi);
        float hA = fmaxf(alo + ahi, 0.f);
        float hB = fmaxf(blo + bhi, 0.f);
        ull hhA = pack2(hA, hA);
        ull hhB = pack2(hB, hB);

        const float* base = sW2T + kk * 16;
        ulonglong2 c0 = *reinterpret_cast<const ulonglong2*>(base);
        ulonglong2 c1 = *reinterpret_cast<const ulonglong2*>(base + 4);
        ulonglong2 c2 = *reinterpret_cast<const ulonglong2*>(base + 8);
        ulonglong2 c3 = *reinterpret_cast<const ulonglong2*>(base + 12);
        aA[0] = fma2(c0.x, hhA, aA[0]);  aB[0] = fma2(c0.x, hhB, aB[0]);
        aA[1] = fma2(c0.y, hhA, aA[1]);  aB[1] = fma2(c0.y, hhB, aB[1]);
        aA[2] = fma2(c1.x, hhA, aA[2]);  aB[2] = fma2(c1.x, hhB, aB[2]);
        aA[3] = fma2(c1.y, hhA, aA[3]);  aB[3] = fma2(c1.y, hhB, aB[3]);
        aA[4] = fma2(c2.x, hhA, aA[4]);  aB[4] = fma2(c2.x, hhB, aB[4]);
        aA[5] = fma2(c2.y, hhA, aA[5]);  aB[5] = fma2(c2.y, hhB, aB[5]);
        aA[6] = fma2(c3.x, hhA, aA[6]);  aB[6] = fma2(c3.x, hhB, aB[6]);
        aA[7] = fma2(c3.y, hhA, aA[7]);  aB[7] = fma2(c3.y, hhB, aB[7]);
    }
    float pA[16], pB[16];
#pragma unroll
    for (int j = 0; j < 8; j++) {
        unpack2(aA[j], pA[2 * j], pA[2 * j + 1]);
        unpack2(aB[j], pB[2 * j], pB[2 * j + 1]);
    }

    // stage 1: role-split pair reduce (xor 1): even lane -> row A, odd -> row B
    float t16[16];
#pragma unroll
    for (int j = 0; j < 16; j++) {
        float v = odd ? pA[j] : pB[j];          // give away other row's partial
        float r = __shfl_xor_sync(0xffffffffu, v, 1);
        t16[j] = (odd ? pB[j] : pA[j]) + r;
    }
    // stage 2: combine the two k-halves (xor 16)
#pragma unroll
    for (int j = 0; j < 16; j++)
        t16[j] += __shfl_xor_sync(0xffffffffu, t16[j], 16);

    float2 dm;
    dm.x = odd ? dB.x : dA.x;
    dm.y = odd ? dB.y : dA.y;

    // tanh split across kh: kh=0 computes hh 0-1, kh=1 computes hh 2-3
    int hbase = kh * 2;
    ull km[2];
#pragma unroll
    for (int hh = 0; hh < 2; hh++) {
        int j0 = 4 * (hbase + hh);
        float t0 = tanh_fast(t16[j0]     + sB2[j0]);
        float t1 = tanh_fast(t16[j0 + 1] + sB2[j0 + 1]);
        float t2 = tanh_fast(t16[j0 + 2] + sB2[j0 + 2]);
        float t3 = tanh_fast(t16[j0 + 3] + sB2[j0 + 3]);
        km[hh] = pack2(t0 * dm.x + t1 * dm.y, t2 * dm.x + t3 * dm.y);
    }
    // exchange across kh (xor 16): assemble this row's full k
    ull kmy[4];
    ull ko0 = __shfl_xor_sync(0xffffffffu, km[0], 16);
    ull ko1 = __shfl_xor_sync(0xffffffffu, km[1], 16);
    kmy[hbase]           = km[0];
    kmy[hbase + 1]       = km[1];
    kmy[(hbase ^ 2)]     = ko0;
    kmy[(hbase ^ 2) + 1] = ko1;

    // rebroadcast across xor-1; all lanes end with both rows' k
#pragma unroll
    for (int hh = 0; hh < 4; hh++) {
        ull ko = __shfl_xor_sync(0xffffffffu, kmy[hh], 1);
        kA[hh] = odd ? ko : kmy[hh];
        kB[hh] = odd ? kmy[hh] : ko;
    }
}

__device__ __forceinline__ void substep2(ull* zA, ull* zB,
                                         float2 xaA, float2 xbA, float2 m0A, float2 m1A,
                                         float2 xaB, float2 xbB, float2 m0B, float2 m1B,
                                         float s0,
                                         const float* sW1, const float* sW2T,
                                         const ull* sB1p, const float* sB2,
                                         int kbeg, int odd, int kh) {
    float2 dA1 = dxval(s0,         xaA, xbA, m0A, m1A);
    float2 dA2 = dxval(s0 + 0.25f, xaA, xbA, m0A, m1A);
    float2 dA3 = dxval(s0 + 0.5f,  xaA, xbA, m0A, m1A);
    float2 dB1 = dxval(s0,         xaB, xbB, m0B, m1B);
    float2 dB2 = dxval(s0 + 0.25f, xaB, xbB, m0B, m1B);
    float2 dB3 = dxval(s0 + 0.5f,  xaB, xbB, m0B, m1B);

    const ull C025 = pack2(0.25f, 0.25f);
    const ull C05  = pack2(0.5f, 0.5f);
    const ull C2   = pack2(2.f, 2.f);
    const ull C112 = pack2(1.f / 12.f, 1.f / 12.f);

    ull kcA[4], kcB[4], ksA[4], ksB[4], ztA[4], ztB[4];
    Feval2(zA, zB, dA1, dB1, sW1, sW2T, sB1p, sB2, kbeg, odd, kh, kcA, kcB);
#pragma unroll
    for (int j = 0; j < 4; j++) {
        ksA[j] = kcA[j]; ztA[j] = fma2(C025, kcA[j], zA[j]);
        ksB[j] = kcB[j]; ztB[j] = fma2(C025, kcB[j], zB[j]);
    }
    Feval2(ztA, ztB, dA2, dB2, sW1, sW2T, sB1p, sB2, kbeg, odd, kh, kcA, kcB);
#pragma unroll
    for (int j = 0; j < 4; j++) {
        ksA[j] = fma2(C2, kcA[j], ksA[j]); ztA[j] = fma2(C025, kcA[j], zA[j]);
        ksB[j] = fma2(C2, kcB[j], ksB[j]); ztB[j] = fma2(C025, kcB[j], zB[j]);
    }
    Feval2(ztA, ztB, dA2, dB2, sW1, sW2T, sB1p, sB2, kbeg, odd, kh, kcA, kcB);
#pragma unroll
    for (int j = 0; j < 4; j++) {
        ksA[j] = fma2(C2, kcA[j], ksA[j]); ztA[j] = fma2(C05, kcA[j], zA[j]);
        ksB[j] = fma2(C2, kcB[j], ksB[j]); ztB[j] = fma2(C05, kcB[j], zB[j]);
    }
    Feval2(ztA, ztB, dA3, dB3, sW1, sW2T, sB1p, sB2, kbeg, odd, kh, kcA, kcB);
#pragma unroll
    for (int j = 0; j < 4; j++) {
        zA[j] = fma2(C112, add2(ksA[j], kcA[j]), zA[j]);
        zB[j] = fma2(C112, add2(ksB[j], kcB[j]), zB[j]);
    }
}

__global__ void __launch_bounds__(32, 8)
k1_ode(const float* __restrict__ X_in, const float* __restrict__ fa_in,
       const int* __restrict__ fa_len,
       const float* __restrict__ W_init, const float* __restrict__ b_init,
       const float* __restrict__ W1, const float* __restrict__ b1,
       const float* __restrict__ W2, const float* __restrict__ b2) {
    __shared__ __align__(16) float sW1[256 * 8];
    __shared__ __align__(16) float sW2T[256 * 16];
    __shared__ __align__(16) ull   sB1p[256];   // (b1, 0) packed
    __shared__ float sB2[16];
    __shared__ float sWI[16];
    __shared__ float sBI[8];
    __shared__ float2 sX[16][33];

    int tid = threadIdx.x;   // 0..31
    for (int i = tid; i < 256 * 8; i += 32) sW1[i] = W1[i];
    // W2 is (16,256); store transposed [k][j]
    for (int i = tid; i < 16 * 256; i += 32) {
        int j = i >> 8;    // 0..15
        int k = i & 255;   // 0..255
        sW2T[k * 16 + j] = W2[i];
    }
    for (int i = tid; i < 256; i += 32) sB1p[i] = pack2(b1[i], 0.f);
    if (tid < 16) sB2[tid] = b2[tid];
    if (tid < 16) sWI[tid] = W_init[tid];
    if (tid < 8)  sBI[tid] = b_init[tid];

    int g  = tid & 1;            // k-parity within half (stride 2)
    int kh = (tid >> 4) & 1;     // k-half: 0 -> [0,128), 1 -> [128,256)
    int p  = (tid >> 1) & 7;     // pair id, 0..7
    int kbeg = kh * 128 + g;
    int q0 = g + 2 * kh;         // 0..3: this lane's slot among the row's 4 lanes
    int rowA = blockIdx.x * 16 + p;
    int rowB = rowA + 8;

    // prologue for both rows: mean, normalize, push-zeros-as-shift
#pragma unroll
    for (int rr = 0; rr < 2; rr++) {
        int row = rr ? rowB : rowA;
        int rib = rr ? (p + 8) : p;
        const float* Xr = X_in + row * LL;
        const float* Fr = fa_in + row * LL;
        int fl = fa_len[row];

        float s = 0.f;
        for (int t = q0; t < LL; t += 4) s += Xr[t];
        s += __shfl_xor_sync(0xffffffffu, s, 1);
        s += __shfl_xor_sync(0xffffffffu, s, 16);
        float mean = s / (float)fl;

        int shift = LL - fl;
        int li = 2 * fl - LL - 1;
        float lastX = (li >= 0) ? (Xr[li] / mean) : 0.f;
        float lastF = Fr[fl - 1];

        for (int q = q0; q < LL; q += 4) {
            float fa, xx;
            if (q < shift) { fa = lastF; xx = lastX; }
            else           { fa = Fr[q - shift]; xx = Xr[q - shift] / mean; }
            sX[rib][q] = make_float2(fa, xx);
        }
    }
    __syncwarp();

    float2 x0A = sX[p][0];
    float2 x0B = sX[p + 8][0];
    ull zA[4], zB[4];
#pragma unroll
    for (int j = 0; j < 4; j++) {
        float a0 = sBI[2 * j]     + sWI[4 * j]     * x0A.x + sWI[4 * j + 1] * x0A.y;
        float a1 = sBI[2 * j + 1] + sWI[4 * j + 2] * x0A.x + sWI[4 * j + 3] * x0A.y;
        zA[j] = pack2(a0, a1);
        float b0 = sBI[2 * j]     + sWI[4 * j]     * x0B.x + sWI[4 * j + 1] * x0B.y;
        float b1v = sBI[2 * j + 1] + sWI[4 * j + 2] * x0B.x + sWI[4 * j + 3] * x0B.y;
        zB[j] = pack2(b0, b1v);
    }

    float2 xaA = x0A, m0A = make_float2(0.f, 0.f), m1A;
    float2 xaB = x0B, m0B = make_float2(0.f, 0.f), m1B;
    for (int i = 0; i < LL - 1; i++) {
        float2 xbA = sX[p][i + 1];
        float2 xbB = sX[p + 8][i + 1];
        m1A.x = xbA.x - xaA.x;  m1A.y = xbA.y - xaA.y;
        m1B.x = xbB.x - xaB.x;  m1B.y = xbB.y - xaB.y;
        if (i == 0) { m0A = m1A; m0B = m1B; }
        substep2(zA, zB, xaA, xbA, m0A, m1A, xaB, xbB, m0B, m1B, 0.0f,
                 sW1, sW2T, sB1p, sB2, kbeg, g, kh);
        substep2(zA, zB, xaA, xbA, m0A, m1A, xaB, xbB, m0B, m1B, 0.5f,
                 sW1, sW2T, sB1p, sB2, kbeg, g, kh);
        m0A = m1A; m0B = m1B;
        xaA = xbA; xaB = xbB;
    }
    // all 4 lanes of the row hold identical z; lane slot q0 writes [2q0, 2q0+1]
    {
        float a0, a1, b0, b1v;
        unpack2(zA[q0], a0, a1);
        unpack2(zB[q0], b0, b1v);
        g_z[rowA * 8 + 2 * q0]     = a0;
        g_z[rowA * 8 + 2 * q0 + 1] = a1;
        g_z[rowB * 8 + 2 * q0]     = b0;
        g_z[rowB * 8 + 2 * q0 + 1] = b1v;
    }
}

// ---------------- k2: readout MLP with smem-cached Wr2 ----------------
#define K2_W2   0                    // 200*201 floats
#define K2_W1   (200 * 201)          // 1600
#define K2_B1   (K2_W1 + 1600)       // 200
#define K2_B2   (K2_B1 + 200)        // 200
#define K2_W3   (K2_B2 + 200)        // 200
#define K2_H1   (K2_W3 + 200)        // 8 warps * 1600
#define K2_SMEM_FLOATS (K2_H1 + 8 * 1600)
#define K2_SMEM_BYTES  (K2_SMEM_FLOATS * 4)

__global__ void __launch_bounds__(256, 1)
k2_readout(const float* __restrict__ Wr1, const float* __restrict__ br1,
           const float* __restrict__ Wr2, const float* __restrict__ br2,
           const float* __restrict__ Wr3, const float* __restrict__ br3) {
    extern __shared__ __align__(16) float sm[];
    int tid = threadIdx.x;
    int lane = tid & 31;
    int w = tid >> 5;

    for (int i = tid; i < 200 * 200; i += 256)
        sm[K2_W2 + (i / 200) * 201 + (i % 200)] = Wr2[i];
    for (int i = tid; i < 1600; i += 256) sm[K2_W1 + i] = Wr1[i];
    for (int i = tid; i < 200; i += 256) {
        sm[K2_B1 + i] = br1[i];
        sm[K2_B2 + i] = br2[i];
        sm[K2_W3 + i] = Wr3[i];
    }
    __syncthreads();

    float* h1w = sm + K2_H1 + w * 1600;
    float b3 = __ldg(br3);

    for (int pass = 0; pass < 2; pass++) {
        int row0 = blockIdx.x * 128 + w * 16 + pass * 8;

        float z8[8][8];
#pragma unroll
        for (int r = 0; r < 8; r++) {
            const float4* zp = reinterpret_cast<const float4*>(g_z + (row0 + r) * 8);
            float4 u = zp[0], v = zp[1];
            z8[r][0] = u.x; z8[r][1] = u.y; z8[r][2] = u.z; z8[r][3] = u.w;
            z8[r][4] = v.x; z8[r][5] = v.y; z8[r][6] = v.z; z8[r][7] = v.w;
        }
        for (int j = lane; j < 200; j += 32) {
            const float4* wp = reinterpret_cast<const float4*>(sm + K2_W1 + j * 8);
            float4 a = wp[0], b = wp[1];
            float bj = sm[K2_B1 + j];
#pragma unroll
            for (int r = 0; r < 8; r++) {
                float h = bj;
                h = fmaf(a.x, z8[r][0], h); h = fmaf(a.y, z8[r][1], h);
                h = fmaf(a.z, z8[r][2], h); h = fmaf(a.w, z8[r][3], h);
                h = fmaf(b.x, z8[r][4], h); h = fmaf(b.y, z8[r][5], h);
                h = fmaf(b.z, z8[r][6], h); h = fmaf(b.w, z8[r][7], h);
                h1w[j * 8 + r] = h * normcdff(h);
            }
        }
        __syncwarp();

        ull acc[7][4];
#pragma unroll
        for (int u = 0; u < 7; u++)
#pragma unroll
            for (int q = 0; q < 4; q++) acc[u][q] = 0ull;

        for (int q = 0; q < 200; q++) {
            const ull* hp = reinterpret_cast<const ull*>(h1w + q * 8);
            ull h01 = hp[0], h23 = hp[1], h45 = hp[2], h67 = hp[3];
#pragma unroll
            for (int u = 0; u < 7; u++) {
                int j = lane + 32 * u;
                float wv = (j < 200) ? sm[K2_W2 + j * 201 + q] : 0.f;
                ull w2 = pack2(wv, wv);
                acc[u][0] = fma2(w2, h01, acc[u][0]);
                acc[u][1] = fma2(w2, h23, acc[u][1]);
                acc[u][2] = fma2(w2, h45, acc[u][2]);
                acc[u][3] = fma2(w2, h67, acc[u][3]);
            }
        }

        float part[8];
#pragma unroll
        for (int r = 0; r < 8; r++) part[r] = 0.f;
#pragma unroll
        for (int u = 0; u < 7; u++) {
            int j = lane + 32 * u;
            if (j < 200) {
                float w3 = sm[K2_W3 + j];
                float b2j = sm[K2_B2 + j];
#pragma unroll
                for (int q = 0; q < 4; q++) {
                    float v0, v1; unpack2(acc[u][q], v0, v1);
                    v0 += b2j; v1 += b2j;
                    part[2 * q]     = fmaf(w3, v0 * normcdff(v0), part[2 * q]);
                    part[2 * q + 1] = fmaf(w3, v1 * normcdff(v1), part[2 * q + 1]);
                }
            }
        }
#pragma unroll
        for (int r = 0; r < 8; r++)
#pragma unroll
            for (int m = 16; m >= 1; m >>= 1)
                part[r] += __shfl_xor_sync(0xffffffffu, part[r], m);

        if (lane < 8) {
            float t = part[lane] + b3;
            float sg = 1.0f / (1.0f + expf(-t));
            g_T10[row0 + lane] = 0.1f + sg * (7.0f - 0.1f);
        }
        __syncwarp();
    }
}

__global__ void __launch_bounds__(128)
k3_out(const float* __restrict__ fa_in, const float* __restrict__ TR,
       const int* __restrict__ fa_len, float* __restrict__ out) {
    int lane = threadIdx.x & 31;
    int w = threadIdx.x >> 5;
    int row = blockIdx.x * 4 + w;

    float T10 = g_T10[row];
    float R1 = 1.0f / T10;
    float E = expf(-TR[row] * R1);
    float fa = fa_in[row * LL + lane];
    float xo = (1.0f - E) * sinf(fa) / (1.0f - cosf(fa) * E);

    float ssum = xo;
#pragma unroll
    for (int m = 16; m >= 1; m >>= 1) ssum += __shfl_xor_sync(0xffffffffu, ssum, m);

    float fl = (float)fa_len[row];
    out[row * LL + lane] = xo * fl / ssum;
    if (lane == 0) {
        out[BB * LL + row] = T10;       // T10
        out[BB * LL + BB + row] = 1.0f; // M0
    }
}

extern "C" void kernel_launch(void* const* d_in, const int* in_sizes, int n_in,
                              void* d_out, int out_size) {
    const float* X_fa_in    = (const float*)d_in[0];
    const float* fa_vals_in = (const float*)d_in[1];
    const float* TR_vals    = (const float*)d_in[2];
    const float* W_init     = (const float*)d_in[3];
    const float* b_init     = (const float*)d_in[4];
    const float* W1         = (const float*)d_in[5];
    const float* b1         = (const float*)d_in[6];
    const float* W2         = (const float*)d_in[7];
    const float* b2         = (const float*)d_in[8];
    const float* Wr1        = (const float*)d_in[9];
    const float* br1        = (const float*)d_in[10];
    const float* Wr2        = (const float*)d_in[11];
    const float* br2        = (const float*)d_in[12];
    const float* Wr3        = (const float*)d_in[13];
    const float* br3        = (const float*)d_in[14];
    // d_in[15] = fa_mask (unused)
    const int*   fa_len     = (const int*)d_in[16];

    float* out = (float*)d_out;

    // host-state op (not a stream op): capture-safe, deterministic, no alloc
    cudaFuncSetAttribute(k2_readout, cudaFuncAttributeMaxDynamicSharedMemorySize,
                         K2_SMEM_BYTES);

    k1_ode<<<BB / 16, 32>>>(X_fa_in, fa_vals_in, fa_len, W_init, b_init, W1, b1, W2, b2);
    k2_readout<<<128, 256, K2_SMEM_BYTES>>>(Wr1, br1, Wr2, br2, Wr3, br3);
    k3_out<<<BB / 4, 128>>>(fa_vals_in, TR_vals, fa_len, out);
}

// round 10
// speedup vs baseline: 1.1995x; 1.0089x over previous
#include <cuda_runtime.h>
#include <cuda_bf16.h>
#include <math.h>

#define BB 16384
#define LL 32

typedef unsigned long long ull;

// scratch (no allocation allowed)
__device__ float g_z[BB * 8];
__device__ float g_T10[BB];

__device__ __forceinline__ ull pack2(float lo, float hi) {
    ull r; asm("mov.b64 %0,{%1,%2};" : "=l"(r) : "f"(lo), "f"(hi)); return r;
}
__device__ __forceinline__ void unpack2(ull v, float& lo, float& hi) {
    asm("mov.b64 {%0,%1},%2;" : "=f"(lo), "=f"(hi) : "l"(v));
}
__device__ __forceinline__ ull fma2(ull a, ull b, ull c) {
    ull d; asm("fma.rn.f32x2 %0,%1,%2,%3;" : "=l"(d) : "l"(a), "l"(b), "l"(c)); return d;
}
__device__ __forceinline__ ull add2(ull a, ull b) {
    ull d; asm("add.rn.f32x2 %0,%1,%2;" : "=l"(d) : "l"(a), "l"(b)); return d;
}

__device__ __forceinline__ float tanh_fast(float x) {
    float e = __expf(2.0f * x);
    return 1.0f - __fdividef(2.0f, e + 1.0f);
}

__device__ __forceinline__ float2 dxval(float s, float2 x0, float2 x1, float2 m0, float2 m1) {
    float s2 = s * s;
    float cx0 = 6.f * s2 - 6.f * s;
    float cm0 = 3.f * s2 - 4.f * s + 1.f;
    float cx1 = -6.f * s2 + 6.f * s;
    float cm1 = 3.f * s2 - 2.f * s;
    float2 r;
    r.x = cx0 * x0.x + cm0 * m0.x + cx1 * x1.x + cm1 * m1.x;
    r.y = cx0 * x0.y + cm0 * m0.y + cx1 * x1.y + cm1 * m1.y;
    return r;
}

// Conflict-free padded weight layout:
//  W2T half kh at base kh*2052 floats (bank shift 4) -> LDS banks 4kh+16g: {0,4,16,20}
//  W1  half kh at base kh*1028 floats                -> banks 4kh+8g: {0,4,8,12}
//  B1p half kh at base kh*130 ulls                   -> bank starts {0,2,4,6}
// Every weight LDS is exactly one wavefront.
__device__ __forceinline__ void Feval2(const ull* zA, const ull* zB,
                                       float2 dA, float2 dB,
                                       const float* w1p, const float* w2p,
                                       const ull* b1p, const float* sB2,
                                       int odd, int kh,
                                       ull* kA, ull* kB) {
    ull aA[8], aB[8];
#pragma unroll
    for (int j = 0; j < 8; j++) { aA[j] = 0ull; aB[j] = 0ull; }

#pragma unroll 4
    for (int t = 0; t < 64; t++) {
        ulonglong2 w1a = *reinterpret_cast<const ulonglong2*>(w1p + t * 16);
        ulonglong2 w1b = *reinterpret_cast<const ulonglong2*>(w1p + t * 16 + 4);
        ull bk = b1p[t * 2];

        ull accA = fma2(w1a.x, zA[0], bk);
        ull accB = fma2(w1a.x, zB[0], bk);
        accA = fma2(w1a.y, zA[1], accA);
        accB = fma2(w1a.y, zB[1], accB);
        accA = fma2(w1b.x, zA[2], accA);
        accB = fma2(w1b.x, zB[2], accB);
        accA = fma2(w1b.y, zA[3], accA);
        accB = fma2(w1b.y, zB[3], accB);
        float alo, ahi, blo, bhi;
        unpack2(accA, alo, ahi);
        unpack2(accB, blo, bhi);
        float hA = fmaxf(alo + ahi, 0.f);
        float hB = fmaxf(blo + bhi, 0.f);
        ull hhA = pack2(hA, hA);
        ull hhB = pack2(hB, hB);

        const float* base = w2p + t * 32;
        ulonglong2 c0 = *reinterpret_cast<const ulonglong2*>(base);
        ulonglong2 c1 = *reinterpret_cast<const ulonglong2*>(base + 4);
        ulonglong2 c2 = *reinterpret_cast<const ulonglong2*>(base + 8);
        ulonglong2 c3 = *reinterpret_cast<const ulonglong2*>(base + 12);
        aA[0] = fma2(c0.x, hhA, aA[0]);  aB[0] = fma2(c0.x, hhB, aB[0]);
        aA[1] = fma2(c0.y, hhA, aA[1]);  aB[1] = fma2(c0.y, hhB, aB[1]);
        aA[2] = fma2(c1.x, hhA, aA[2]);  aB[2] = fma2(c1.x, hhB, aB[2]);
        aA[3] = fma2(c1.y, hhA, aA[3]);  aB[3] = fma2(c1.y, hhB, aB[3]);
        aA[4] = fma2(c2.x, hhA, aA[4]);  aB[4] = fma2(c2.x, hhB, aB[4]);
        aA[5] = fma2(c2.y, hhA, aA[5]);  aB[5] = fma2(c2.y, hhB, aB[5]);
        aA[6] = fma2(c3.x, hhA, aA[6]);  aB[6] = fma2(c3.x, hhB, aB[6]);
        aA[7] = fma2(c3.y, hhA, aA[7]);  aB[7] = fma2(c3.y, hhB, aB[7]);
    }
    float pA[16], pB[16];
#pragma unroll
    for (int j = 0; j < 8; j++) {
        unpack2(aA[j], pA[2 * j], pA[2 * j + 1]);
        unpack2(aB[j], pB[2 * j], pB[2 * j + 1]);
    }

    // stage 1: role-split pair reduce (xor 1): even lane -> row A, odd -> row B
    float t16[16];
#pragma unroll
    for (int j = 0; j < 16; j++) {
        float v = odd ? pA[j] : pB[j];          // give away other row's partial
        float r = __shfl_xor_sync(0xffffffffu, v, 1);
        t16[j] = (odd ? pB[j] : pA[j]) + r;
    }
    // stage 2: combine the two k-halves (xor 16)
#pragma unroll
    for (int j = 0; j < 16; j++)
        t16[j] += __shfl_xor_sync(0xffffffffu, t16[j], 16);

    float2 dm;
    dm.x = odd ? dB.x : dA.x;
    dm.y = odd ? dB.y : dA.y;

    // tanh split across kh: kh=0 computes hh 0-1, kh=1 computes hh 2-3
    int hbase = kh * 2;
    ull km[2];
#pragma unroll
    for (int hh = 0; hh < 2; hh++) {
        int j0 = 4 * (hbase + hh);
        float t0 = tanh_fast(t16[j0]     + sB2[j0]);
        float t1 = tanh_fast(t16[j0 + 1] + sB2[j0 + 1]);
        float t2 = tanh_fast(t16[j0 + 2] + sB2[j0 + 2]);
        float t3 = tanh_fast(t16[j0 + 3] + sB2[j0 + 3]);
        km[hh] = pack2(t0 * dm.x + t1 * dm.y, t2 * dm.x + t3 * dm.y);
    }
    // exchange across kh (xor 16): assemble this row's full k
    ull kmy[4];
    ull ko0 = __shfl_xor_sync(0xffffffffu, km[0], 16);
    ull ko1 = __shfl_xor_sync(0xffffffffu, km[1], 16);
    kmy[hbase]           = km[0];
    kmy[hbase + 1]       = km[1];
    kmy[(hbase ^ 2)]     = ko0;
    kmy[(hbase ^ 2) + 1] = ko1;

    // rebroadcast across xor-1; all lanes end with both rows' k
#pragma unroll
    for (int hh = 0; hh < 4; hh++) {
        ull ko = __shfl_xor_sync(0xffffffffu, kmy[hh], 1);
        kA[hh] = odd ? ko : kmy[hh];
        kB[hh] = odd ? kmy[hh] : ko;
    }
}

__device__ __forceinline__ void substep2(ull* zA, ull* zB,
                                         float2 xaA, float2 xbA, float2 m0A, float2 m1A,
                                         float2 xaB, float2 xbB, float2 m0B, float2 m1B,
                                         float s0,
                                         const float* w1p, const float* w2p,
                                         const ull* b1p, const float* sB2,
                                         int odd, int kh) {
    float2 dA1 = dxval(s0,         xaA, xbA, m0A, m1A);
    float2 dA2 = dxval(s0 + 0.25f, xaA, xbA, m0A, m1A);
    float2 dA3 = dxval(s0 + 0.5f,  xaA, xbA, m0A, m1A);
    float2 dB1 = dxval(s0,         xaB, xbB, m0B, m1B);
    float2 dB2 = dxval(s0 + 0.25f, xaB, xbB, m0B, m1B);
    float2 dB3 = dxval(s0 + 0.5f,  xaB, xbB, m0B, m1B);

    const ull C025 = pack2(0.25f, 0.25f);
    const ull C05  = pack2(0.5f, 0.5f);
    const ull C2   = pack2(2.f, 2.f);
    const ull C112 = pack2(1.f / 12.f, 1.f / 12.f);

    ull kcA[4], kcB[4], ksA[4], ksB[4], ztA[4], ztB[4];
    Feval2(zA, zB, dA1, dB1, w1p, w2p, b1p, sB2, odd, kh, kcA, kcB);
#pragma unroll
    for (int j = 0; j < 4; j++) {
        ksA[j] = kcA[j]; ztA[j] = fma2(C025, kcA[j], zA[j]);
        ksB[j] = kcB[j]; ztB[j] = fma2(C025, kcB[j], zB[j]);
    }
    Feval2(ztA, ztB, dA2, dB2, w1p, w2p, b1p, sB2, odd, kh, kcA, kcB);
#pragma unroll
    for (int j = 0; j < 4; j++) {
        ksA[j] = fma2(C2, kcA[j], ksA[j]); ztA[j] = fma2(C025, kcA[j], zA[j]);
        ksB[j] = fma2(C2, kcB[j], ksB[j]); ztB[j] = fma2(C025, kcB[j], zB[j]);
    }
    Feval2(ztA, ztB, dA2, dB2, w1p, w2p, b1p, sB2, odd, kh, kcA, kcB);
#pragma unroll
    for (int j = 0; j < 4; j++) {
        ksA[j] = fma2(C2, kcA[j], ksA[j]); ztA[j] = fma2(C05, kcA[j], zA[j]);
        ksB[j] = fma2(C2, kcB[j], ksB[j]); ztB[j] = fma2(C05, kcB[j], zB[j]);
    }
    Feval2(ztA, ztB, dA3, dB3, w1p, w2p, b1p, sB2, odd, kh, kcA, kcB);
#pragma unroll
    for (int j = 0; j < 4; j++) {
        zA[j] = fma2(C112, add2(ksA[j], kcA[j]), zA[j]);
        zB[j] = fma2(C112, add2(ksB[j], kcB[j]), zB[j]);
    }
}

__global__ void __launch_bounds__(32, 8)
k1_ode(const float* __restrict__ X_in, const float* __restrict__ fa_in,
       const int* __restrict__ fa_len,
       const float* __restrict__ W_init, const float* __restrict__ b_init,
       const float* __restrict__ W1, const float* __restrict__ b1,
       const float* __restrict__ W2, const float* __restrict__ b2) {
    // padded layouts: kh half-blocks bank-shifted by 16 B
    __shared__ __align__(16) float sW1[2052];    // 2 halves * 128 rows * 8, +4 pad
    __shared__ __align__(16) float sW2T[4100];   // 2 halves * 128 rows * 16, +4 pad
    __shared__ __align__(16) ull   sB1p[258];    // 2 halves * 128, +2 pad
    __shared__ float sB2[16];
    __shared__ float sWI[16];
    __shared__ float sBI[8];
    __shared__ float2 sX[16][33];

    int tid = threadIdx.x;   // 0..31
    for (int i = tid; i < 2048; i += 32) {
        int kk = i >> 3, e = i & 7;
        int h = kk >> 7, jr = kk & 127;
        sW1[h * 1028 + jr * 8 + e] = W1[i];
    }
    // W2 is (16,256); store transposed [k][j] with half-block padding
    for (int i = tid; i < 16 * 256; i += 32) {
        int j = i >> 8;    // 0..15
        int k = i & 255;   // 0..255
        int h = k >> 7, jr = k & 127;
        sW2T[h * 2052 + jr * 16 + j] = W2[i];
    }
    for (int i = tid; i < 256; i += 32) {
        int h = i >> 7, jr = i & 127;
        sB1p[h * 130 + jr] = pack2(b1[i], 0.f);
    }
    if (tid < 16) sB2[tid] = b2[tid];
    if (tid < 16) sWI[tid] = W_init[tid];
    if (tid < 8)  sBI[tid] = b_init[tid];

    int g  = tid & 1;            // k-parity within half (stride 2)
    int kh = (tid >> 4) & 1;     // k-half: 0 -> [0,128), 1 -> [128,256)
    int p  = (tid >> 1) & 7;     // pair id, 0..7
    int q0 = g + 2 * kh;         // 0..3: this lane's slot among the row's 4 lanes
    int rowA = blockIdx.x * 16 + p;
    int rowB = rowA + 8;

    // per-lane conflict-free weight pointers
    const float* w2p = sW2T + kh * 2052 + g * 16;
    const float* w1p = sW1  + kh * 1028 + g * 8;
    const ull*   b1p = sB1p + kh * 130  + g;

    // prologue for both rows: mean, normalize, push-zeros-as-shift
#pragma unroll
    for (int rr = 0; rr < 2; rr++) {
        int row = rr ? rowB : rowA;
        int rib = rr ? (p + 8) : p;
        const float* Xr = X_in + row * LL;
        const float* Fr = fa_in + row * LL;
        int fl = fa_len[row];

        float s = 0.f;
        for (int t = q0; t < LL; t += 4) s += Xr[t];
        s += __shfl_xor_sync(0xffffffffu, s, 1);
        s += __shfl_xor_sync(0xffffffffu, s, 16);
        float mean = s / (float)fl;

        int shift = LL - fl;
        int li = 2 * fl - LL - 1;
        float lastX = (li >= 0) ? (Xr[li] / mean) : 0.f;
        float lastF = Fr[fl - 1];

        for (int q = q0; q < LL; q += 4) {
            float fa, xx;
            if (q < shift) { fa = lastF; xx = lastX; }
            else           { fa = Fr[q - shift]; xx = Xr[q - shift] / mean; }
            sX[rib][q] = make_float2(fa, xx);
        }
    }
    __syncwarp();

    float2 x0A = sX[p][0];
    float2 x0B = sX[p + 8][0];
    ull zA[4], zB[4];
#pragma unroll
    for (int j = 0; j < 4; j++) {
        float a0 = sBI[2 * j]     + sWI[4 * j]     * x0A.x + sWI[4 * j + 1] * x0A.y;
        float a1 = sBI[2 * j + 1] + sWI[4 * j + 2] * x0A.x + sWI[4 * j + 3] * x0A.y;
        zA[j] = pack2(a0, a1);
        float b0 = sBI[2 * j]     + sWI[4 * j]     * x0B.x + sWI[4 * j + 1] * x0B.y;
        float b1v = sBI[2 * j + 1] + sWI[4 * j + 2] * x0B.x + sWI[4 * j + 3] * x0B.y;
        zB[j] = pack2(b0, b1v);
    }

    float2 xaA = x0A, m0A = make_float2(0.f, 0.f), m1A;
    float2 xaB = x0B, m0B = make_float2(0.f, 0.f), m1B;
    for (int i = 0; i < LL - 1; i++) {
        float2 xbA = sX[p][i + 1];
        float2 xbB = sX[p + 8][i + 1];
        m1A.x = xbA.x - xaA.x;  m1A.y = xbA.y - xaA.y;
        m1B.x = xbB.x - xaB.x;  m1B.y = xbB.y - xaB.y;
        if (i == 0) { m0A = m1A; m0B = m1B; }
        substep2(zA, zB, xaA, xbA, m0A, m1A, xaB, xbB, m0B, m1B, 0.0f,
                 w1p, w2p, b1p, sB2, g, kh);
        substep2(zA, zB, xaA, xbA, m0A, m1A, xaB, xbB, m0B, m1B, 0.5f,
                 w1p, w2p, b1p, sB2, g, kh);
        m0A = m1A; m0B = m1B;
        xaA = xbA; xaB = xbB;
    }
    // all 4 lanes of the row hold identical z; lane slot q0 writes [2q0, 2q0+1]
    {
        float a0, a1, b0, b1v;
        unpack2(zA[q0], a0, a1);
        unpack2(zB[q0], b0, b1v);
        g_z[rowA * 8 + 2 * q0]     = a0;
        g_z[rowA * 8 + 2 * q0 + 1] = a1;
        g_z[rowB * 8 + 2 * q0]     = b0;
        g_z[rowB * 8 + 2 * q0 + 1] = b1v;
    }
}

// ---------------- k2: readout MLP with smem-cached Wr2 ----------------
#define K2_W2   0                    // 200*201 floats
#define K2_W1   (200 * 201)          // 1600
#define K2_B1   (K2_W1 + 1600)       // 200
#define K2_B2   (K2_B1 + 200)        // 200
#define K2_W3   (K2_B2 + 200)        // 200
#define K2_H1   (K2_W3 + 200)        // 8 warps * 1600
#define K2_SMEM_FLOATS (K2_H1 + 8 * 1600)
#define K2_SMEM_BYTES  (K2_SMEM_FLOATS * 4)

__global__ void __launch_bounds__(256, 1)
k2_readout(const float* __restrict__ Wr1, const float* __restrict__ br1,
           const float* __restrict__ Wr2, const float* __restrict__ br2,
           const float* __restrict__ Wr3, const float* __restrict__ br3) {
    extern __shared__ __align__(16) float sm[];
    int tid = threadIdx.x;
    int lane = tid & 31;
    int w = tid >> 5;

    for (int i = tid; i < 200 * 200; i += 256)
        sm[K2_W2 + (i / 200) * 201 + (i % 200)] = Wr2[i];
    for (int i = tid; i < 1600; i += 256) sm[K2_W1 + i] = Wr1[i];
    for (int i = tid; i < 200; i += 256) {
        sm[K2_B1 + i] = br1[i];
        sm[K2_B2 + i] = br2[i];
        sm[K2_W3 + i] = Wr3[i];
    }
    __syncthreads();

    float* h1w = sm + K2_H1 + w * 1600;
    float b3 = __ldg(br3);

    for (int pass = 0; pass < 2; pass++) {
        int row0 = blockIdx.x * 128 + w * 16 + pass * 8;

        float z8[8][8];
#pragma unroll
        for (int r = 0; r < 8; r++) {
            const float4* zp = reinterpret_cast<const float4*>(g_z + (row0 + r) * 8);
            float4 u = zp[0], v = zp[1];
            z8[r][0] = u.x; z8[r][1] = u.y; z8[r][2] = u.z; z8[r][3] = u.w;
            z8[r][4] = v.x; z8[r][5] = v.y; z8[r][6] = v.z; z8[r][7] = v.w;
        }
        for (int j = lane; j < 200; j += 32) {
            const float4* wp = reinterpret_cast<const float4*>(sm + K2_W1 + j * 8);
            float4 a = wp[0], b = wp[1];
            float bj = sm[K2_B1 + j];
#pragma unroll
            for (int r = 0; r < 8; r++) {
                float h = bj;
                h = fmaf(a.x, z8[r][0], h); h = fmaf(a.y, z8[r][1], h);
                h = fmaf(a.z, z8[r][2], h); h = fmaf(a.w, z8[r][3], h);
                h = fmaf(b.x, z8[r][4], h); h = fmaf(b.y, z8[r][5], h);
                h = fmaf(b.z, z8[r][6], h); h = fmaf(b.w, z8[r][7], h);
                h1w[j * 8 + r] = h * normcdff(h);
            }
        }
        __syncwarp();

        ull acc[7][4];
#pragma unroll
        for (int u = 0; u < 7; u++)
#pragma unroll
            for (int q = 0; q < 4; q++) acc[u][q] = 0ull;

        for (int q = 0; q < 200; q++) {
            const ull* hp = reinterpret_cast<const ull*>(h1w + q * 8);
            ull h01 = hp[0], h23 = hp[1], h45 = hp[2], h67 = hp[3];
#pragma unroll
            for (int u = 0; u < 7; u++) {
                int j = lane + 32 * u;
                float wv = (j < 200) ? sm[K2_W2 + j * 201 + q] : 0.f;
                ull w2 = pack2(wv, wv);
                acc[u][0] = fma2(w2, h01, acc[u][0]);
                acc[u][1] = fma2(w2, h23, acc[u][1]);
                acc[u][2] = fma2(w2, h45, acc[u][2]);
                acc[u][3] = fma2(w2, h67, acc[u][3]);
            }
        }

        float part[8];
#pragma unroll
        for (int r = 0; r < 8; r++) part[r] = 0.f;
#pragma unroll
        for (int u = 0; u < 7; u++) {
            int j = lane + 32 * u;
            if (j < 200) {
                float w3 = sm[K2_W3 + j];
                float b2j = sm[K2_B2 + j];
#pragma unroll
                for (int q = 0; q < 4; q++) {
                    float v0, v1; unpack2(acc[u][q], v0, v1);
                    v0 += b2j; v1 += b2j;
                    part[2 * q]     = fmaf(w3, v0 * normcdff(v0), part[2 * q]);
                    part[2 * q + 1] = fmaf(w3, v1 * normcdff(v1), part[2 * q + 1]);
                }
            }
        }
#pragma unroll
        for (int r = 0; r < 8; r++)
#pragma unroll
            for (int m = 16; m >= 1; m >>= 1)
                part[r] += __shfl_xor_sync(0xffffffffu, part[r], m);

        if (lane < 8) {
            float t = part[lane] + b3;
            float sg = 1.0f / (1.0f + expf(-t));
            g_T10[row0 + lane] = 0.1f + sg * (7.0f - 0.1f);
        }
        __syncwarp();
    }
}

__global__ void __launch_bounds__(128)
k3_out(const float* __restrict__ fa_in, const float* __restrict__ TR,
       const int* __restrict__ fa_len, float* __restrict__ out) {
    int lane = threadIdx.x & 31;
    int w = threadIdx.x >> 5;
    int row = blockIdx.x * 4 + w;

    float T10 = g_T10[row];
    float R1 = 1.0f / T10;
    float E = expf(-TR[row] * R1);
    float fa = fa_in[row * LL + lane];
    float xo = (1.0f - E) * sinf(fa) / (1.0f - cosf(fa) * E);

    float ssum = xo;
#pragma unroll
    for (int m = 16; m >= 1; m >>= 1) ssum += __shfl_xor_sync(0xffffffffu, ssum, m);

    float fl = (float)fa_len[row];
    out[row * LL + lane] = xo * fl / ssum;
    if (lane == 0) {
        out[BB * LL + row] = T10;       // T10
        out[BB * LL + BB + row] = 1.0f; // M0
    }
}

extern "C" void kernel_launch(void* const* d_in, const int* in_sizes, int n_in,
                              void* d_out, int out_size) {
    const float* X_fa_in    = (const float*)d_in[0];
    const float* fa_vals_in = (const float*)d_in[1];
    const float* TR_vals    = (const float*)d_in[2];
    const float* W_init     = (const float*)d_in[3];
    const float* b_init     = (const float*)d_in[4];
    const float* W1         = (const float*)d_in[5];
    const float* b1         = (const float*)d_in[6];
    const float* W2         = (const float*)d_in[7];
    const float* b2         = (const float*)d_in[8];
    const float* Wr1        = (const float*)d_in[9];
    const float* br1        = (const float*)d_in[10];
    const float* Wr2        = (const float*)d_in[11];
    const float* br2        = (const float*)d_in[12];
    const float* Wr3        = (const float*)d_in[13];
    const float* br3        = (const float*)d_in[14];
    // d_in[15] = fa_mask (unused)
    const int*   fa_len     = (const int*)d_in[16];

    float* out = (float*)d_out;

    // host-state op (not a stream op): capture-safe, deterministic, no alloc
    cudaFuncSetAttribute(k2_readout, cudaFuncAttributeMaxDynamicSharedMemorySize,
                         K2_SMEM_BYTES);

    k1_ode<<<BB / 16, 32>>>(X_fa_in, fa_vals_in, fa_len, W_init, b_init, W1, b1, W2, b2);
    k2_readout<<<128, 256, K2_SMEM_BYTES>>>(Wr1, br1, Wr2, br2, Wr3, br3);
    k3_out<<<BB / 4, 128>>>(fa_vals_in, TR_vals, fa_len, out);
}

// round 11
// speedup vs baseline: 1.2255x; 1.0217x over previous
#include <cuda_runtime.h>
#include <cuda_bf16.h>
#include <math.h>

#define BB 16384
#define LL 32

typedef unsigned long long ull;

// scratch (no allocation allowed)
__device__ float g_z[BB * 8];
__device__ float g_T10[BB];

__device__ __forceinline__ ull pack2(float lo, float hi) {
    ull r; asm("mov.b64 %0,{%1,%2};" : "=l"(r) : "f"(lo), "f"(hi)); return r;
}
__device__ __forceinline__ void unpack2(ull v, float& lo, float& hi) {
    asm("mov.b64 {%0,%1},%2;" : "=f"(lo), "=f"(hi) : "l"(v));
}
__device__ __forceinline__ ull fma2(ull a, ull b, ull c) {
    ull d; asm("fma.rn.f32x2 %0,%1,%2,%3;" : "=l"(d) : "l"(a), "l"(b), "l"(c)); return d;
}
__device__ __forceinline__ ull add2(ull a, ull b) {
    ull d; asm("add.rn.f32x2 %0,%1,%2;" : "=l"(d) : "l"(a), "l"(b)); return d;
}
__device__ __forceinline__ ull shfl64(ull v, int m) {
    float lo, hi; unpack2(v, lo, hi);
    lo = __shfl_xor_sync(0xffffffffu, lo, m);
    hi = __shfl_xor_sync(0xffffffffu, hi, m);
    return pack2(lo, hi);
}

__device__ __forceinline__ float tanh_fast(float x) {
    float e = __expf(2.0f * x);
    return 1.0f - __fdividef(2.0f, e + 1.0f);
}

__device__ __forceinline__ float2 dxval(float s, float2 x0, float2 x1, float2 m0, float2 m1) {
    float s2 = s * s;
    float cx0 = 6.f * s2 - 6.f * s;
    float cm0 = 3.f * s2 - 4.f * s + 1.f;
    float cx1 = -6.f * s2 + 6.f * s;
    float cm1 = 3.f * s2 - 2.f * s;
    float2 r;
    r.x = cx0 * x0.x + cm0 * m0.x + cx1 * x1.x + cm1 * m1.x;
    r.y = cx0 * x0.y + cm0 * m0.y + cx1 * x1.y + cm1 * m1.y;
    return r;
}

// F(s,z) for TWO rows per lane; warp splits k by lane parity g (stride 2)
// and warp half kh. Packed reduce: stage1 xor-1 role-split on packed
// accumulators (even->rowA, odd->rowB), stage2 xor-16 kh-role-split (each
// lane keeps its j-half). tanh on own half only; k reassembled by shuffles.
__device__ __forceinline__ void Feval2(const ull* zA, const ull* zB,
                                       float2 dA, float2 dB,
                                       const float* w1p, const float* w2p,
                                       const ull* b1p, const float* sB2,
                                       int odd, int kh,
                                       ull* kA, ull* kB) {
    ull aA[8], aB[8];
#pragma unroll
    for (int j = 0; j < 8; j++) { aA[j] = 0ull; aB[j] = 0ull; }

#pragma unroll 8
    for (int t = 0; t < 64; t++) {
        ulonglong2 w1a = *reinterpret_cast<const ulonglong2*>(w1p + t * 16);
        ulonglong2 w1b = *reinterpret_cast<const ulonglong2*>(w1p + t * 16 + 4);
        ull bk = b1p[t * 2];

        ull accA = fma2(w1a.x, zA[0], bk);
        ull accB = fma2(w1a.x, zB[0], bk);
        accA = fma2(w1a.y, zA[1], accA);
        accB = fma2(w1a.y, zB[1], accB);
        accA = fma2(w1b.x, zA[2], accA);
        accB = fma2(w1b.x, zB[2], accB);
        accA = fma2(w1b.y, zA[3], accA);
        accB = fma2(w1b.y, zB[3], accB);
        float alo, ahi, blo, bhi;
        unpack2(accA, alo, ahi);
        unpack2(accB, blo, bhi);
        float hA = fmaxf(alo + ahi, 0.f);
        float hB = fmaxf(blo + bhi, 0.f);
        ull hhA = pack2(hA, hA);
        ull hhB = pack2(hB, hB);

        const float* base = w2p + t * 32;
        ulonglong2 c0 = *reinterpret_cast<const ulonglong2*>(base);
        ulonglong2 c1 = *reinterpret_cast<const ulonglong2*>(base + 4);
        ulonglong2 c2 = *reinterpret_cast<const ulonglong2*>(base + 8);
        ulonglong2 c3 = *reinterpret_cast<const ulonglong2*>(base + 12);
        aA[0] = fma2(c0.x, hhA, aA[0]);  aB[0] = fma2(c0.x, hhB, aB[0]);
        aA[1] = fma2(c0.y, hhA, aA[1]);  aB[1] = fma2(c0.y, hhB, aB[1]);
        aA[2] = fma2(c1.x, hhA, aA[2]);  aB[2] = fma2(c1.x, hhB, aB[2]);
        aA[3] = fma2(c1.y, hhA, aA[3]);  aB[3] = fma2(c1.y, hhB, aB[3]);
        aA[4] = fma2(c2.x, hhA, aA[4]);  aB[4] = fma2(c2.x, hhB, aB[4]);
        aA[5] = fma2(c2.y, hhA, aA[5]);  aB[5] = fma2(c2.y, hhB, aB[5]);
        aA[6] = fma2(c3.x, hhA, aA[6]);  aB[6] = fma2(c3.x, hhB, aB[6]);
        aA[7] = fma2(c3.y, hhA, aA[7]);  aB[7] = fma2(c3.y, hhB, aB[7]);
    }

    // stage 1 (packed): xor-1 role split; even lane keeps row A, odd row B
    ull t8[8];
#pragma unroll
    for (int j = 0; j < 8; j++) {
        ull give = odd ? aA[j] : aB[j];
        ull keep = odd ? aB[j] : aA[j];
        t8[j] = add2(keep, shfl64(give, 1));
    }
    // stage 2 (packed): xor-16 kh role split; lane keeps its j-half
    ull own[4];
#pragma unroll
    for (int i = 0; i < 4; i++) {
        ull give = kh ? t8[i] : t8[4 + i];
        ull keep = kh ? t8[4 + i] : t8[i];
        own[i] = add2(keep, shfl64(give, 16));
    }

    float2 dm;
    dm.x = odd ? dB.x : dA.x;
    dm.y = odd ? dB.y : dA.y;
    const float* b2p = sB2 + 8 * kh;

    // tanh on own half: j = 8kh+2i, 8kh+2i+1  -> k component hh = 4kh+i
    float o[4];
#pragma unroll
    for (int i = 0; i < 4; i++) {
        float u0, u1; unpack2(own[i], u0, u1);
        float t0 = tanh_fast(u0 + b2p[2 * i]);
        float t1 = tanh_fast(u1 + b2p[2 * i + 1]);
        o[i] = t0 * dm.x + t1 * dm.y;
    }
    ull m0 = pack2(o[0], o[1]);   // kmy[2kh]
    ull m1 = pack2(o[2], o[3]);   // kmy[2kh+1]

    // exchange across kh (xor 16): assemble this row's full k
    ull ko0 = shfl64(m0, 16);
    ull ko1 = shfl64(m1, 16);
    ull kmy[4];
    int hb = kh * 2;
    kmy[hb]           = m0;
    kmy[hb + 1]       = m1;
    kmy[hb ^ 2]       = ko0;
    kmy[(hb ^ 2) + 1] = ko1;

    // rebroadcast across xor-1; all lanes end with both rows' k
#pragma unroll
    for (int hh = 0; hh < 4; hh++) {
        ull ko = shfl64(kmy[hh], 1);
        kA[hh] = odd ? ko : kmy[hh];
        kB[hh] = odd ? kmy[hh] : ko;
    }
}

__device__ __forceinline__ void substep2(ull* zA, ull* zB,
                                         float2 xaA, float2 xbA, float2 m0A, float2 m1A,
                                         float2 xaB, float2 xbB, float2 m0B, float2 m1B,
                                         float s0,
                                         const float* w1p, const float* w2p,
                                         const ull* b1p, const float* sB2,
                                         int odd, int kh) {
    float2 dA1 = dxval(s0,         xaA, xbA, m0A, m1A);
    float2 dA2 = dxval(s0 + 0.25f, xaA, xbA, m0A, m1A);
    float2 dA3 = dxval(s0 + 0.5f,  xaA, xbA, m0A, m1A);
    float2 dB1 = dxval(s0,         xaB, xbB, m0B, m1B);
    float2 dB2 = dxval(s0 + 0.25f, xaB, xbB, m0B, m1B);
    float2 dB3 = dxval(s0 + 0.5f,  xaB, xbB, m0B, m1B);

    const ull C025 = pack2(0.25f, 0.25f);
    const ull C05  = pack2(0.5f, 0.5f);
    const ull C2   = pack2(2.f, 2.f);
    const ull C112 = pack2(1.f / 12.f, 1.f / 12.f);

    ull kcA[4], kcB[4], ksA[4], ksB[4], ztA[4], ztB[4];
    Feval2(zA, zB, dA1, dB1, w1p, w2p, b1p, sB2, odd, kh, kcA, kcB);
#pragma unroll
    for (int j = 0; j < 4; j++) {
        ksA[j] = kcA[j]; ztA[j] = fma2(C025, kcA[j], zA[j]);
        ksB[j] = kcB[j]; ztB[j] = fma2(C025, kcB[j], zB[j]);
    }
    Feval2(ztA, ztB, dA2, dB2, w1p, w2p, b1p, sB2, odd, kh, kcA, kcB);
#pragma unroll
    for (int j = 0; j < 4; j++) {
        ksA[j] = fma2(C2, kcA[j], ksA[j]); ztA[j] = fma2(C025, kcA[j], zA[j]);
        ksB[j] = fma2(C2, kcB[j], ksB[j]); ztB[j] = fma2(C025, kcB[j], zB[j]);
    }
    Feval2(ztA, ztB, dA2, dB2, w1p, w2p, b1p, sB2, odd, kh, kcA, kcB);
#pragma unroll
    for (int j = 0; j < 4; j++) {
        ksA[j] = fma2(C2, kcA[j], ksA[j]); ztA[j] = fma2(C05, kcA[j], zA[j]);
        ksB[j] = fma2(C2, kcB[j], ksB[j]); ztB[j] = fma2(C05, kcB[j], zB[j]);
    }
    Feval2(ztA, ztB, dA3, dB3, w1p, w2p, b1p, sB2, odd, kh, kcA, kcB);
#pragma unroll
    for (int j = 0; j < 4; j++) {
        zA[j] = fma2(C112, add2(ksA[j], kcA[j]), zA[j]);
        zB[j] = fma2(C112, add2(ksB[j], kcB[j]), zB[j]);
    }
}

__global__ void __launch_bounds__(32, 8)
k1_ode(const float* __restrict__ X_in, const float* __restrict__ fa_in,
       const int* __restrict__ fa_len,
       const float* __restrict__ W_init, const float* __restrict__ b_init,
       const float* __restrict__ W1, const float* __restrict__ b1,
       const float* __restrict__ W2, const float* __restrict__ b2) {
    // padded layouts: kh half-blocks bank-shifted by 16 B
    __shared__ __align__(16) float sW1[2052];
    __shared__ __align__(16) float sW2T[4100];
    __shared__ __align__(16) ull   sB1p[258];
    __shared__ float sB2[16];
    __shared__ float sWI[16];
    __shared__ float sBI[8];
    __shared__ float2 sX[16][33];

    int tid = threadIdx.x;   // 0..31
    for (int i = tid; i < 2048; i += 32) {
        int kk = i >> 3, e = i & 7;
        int h = kk >> 7, jr = kk & 127;
        sW1[h * 1028 + jr * 8 + e] = W1[i];
    }
    for (int i = tid; i < 16 * 256; i += 32) {
        int j = i >> 8;
        int k = i & 255;
        int h = k >> 7, jr = k & 127;
        sW2T[h * 2052 + jr * 16 + j] = W2[i];
    }
    for (int i = tid; i < 256; i += 32) {
        int h = i >> 7, jr = i & 127;
        sB1p[h * 130 + jr] = pack2(b1[i], 0.f);
    }
    if (tid < 16) sB2[tid] = b2[tid];
    if (tid < 16) sWI[tid] = W_init[tid];
    if (tid < 8)  sBI[tid] = b_init[tid];

    int g  = tid & 1;            // k-parity within half (stride 2)
    int kh = (tid >> 4) & 1;     // k-half
    int p  = (tid >> 1) & 7;     // pair id, 0..7
    int q0 = g + 2 * kh;         // lane's slot among the row's 4 lanes
    int rowA = blockIdx.x * 16 + p;
    int rowB = rowA + 8;

    const float* w2p = sW2T + kh * 2052 + g * 16;
    const float* w1p = sW1  + kh * 1028 + g * 8;
    const ull*   b1p = sB1p + kh * 130  + g;

    // prologue for both rows: mean, normalize, push-zeros-as-shift
#pragma unroll
    for (int rr = 0; rr < 2; rr++) {
        int row = rr ? rowB : rowA;
        int rib = rr ? (p + 8) : p;
        const float* Xr = X_in + row * LL;
        const float* Fr = fa_in + row * LL;
        int fl = fa_len[row];

        float s = 0.f;
        for (int t = q0; t < LL; t += 4) s += Xr[t];
        s += __shfl_xor_sync(0xffffffffu, s, 1);
        s += __shfl_xor_sync(0xffffffffu, s, 16);
        float mean = s / (float)fl;

        int shift = LL - fl;
        int li = 2 * fl - LL - 1;
        float lastX = (li >= 0) ? (Xr[li] / mean) : 0.f;
        float lastF = Fr[fl - 1];

        for (int q = q0; q < LL; q += 4) {
            float fa, xx;
            if (q < shift) { fa = lastF; xx = lastX; }
            else           { fa = Fr[q - shift]; xx = Xr[q - shift] / mean; }
            sX[rib][q] = make_float2(fa, xx);
        }
    }
    __syncwarp();

    float2 x0A = sX[p][0];
    float2 x0B = sX[p + 8][0];
    ull zA[4], zB[4];
#pragma unroll
    for (int j = 0; j < 4; j++) {
        float a0 = sBI[2 * j]     + sWI[4 * j]     * x0A.x + sWI[4 * j + 1] * x0A.y;
        float a1 = sBI[2 * j + 1] + sWI[4 * j + 2] * x0A.x + sWI[4 * j + 3] * x0A.y;
        zA[j] = pack2(a0, a1);
        float b0 = sBI[2 * j]     + sWI[4 * j]     * x0B.x + sWI[4 * j + 1] * x0B.y;
        float b1v = sBI[2 * j + 1] + sWI[4 * j + 2] * x0B.x + sWI[4 * j + 3] * x0B.y;
        zB[j] = pack2(b0, b1v);
    }

    float2 xaA = x0A, m0A = make_float2(0.f, 0.f), m1A;
    float2 xaB = x0B, m0B = make_float2(0.f, 0.f), m1B;
    for (int i = 0; i < LL - 1; i++) {
        float2 xbA = sX[p][i + 1];
        float2 xbB = sX[p + 8][i + 1];
        m1A.x = xbA.x - xaA.x;  m1A.y = xbA.y - xaA.y;
        m1B.x = xbB.x - xaB.x;  m1B.y = xbB.y - xaB.y;
        if (i == 0) { m0A = m1A; m0B = m1B; }
        substep2(zA, zB, xaA, xbA, m0A, m1A, xaB, xbB, m0B, m1B, 0.0f,
                 w1p, w2p, b1p, sB2, g, kh);
        substep2(zA, zB, xaA, xbA, m0A, m1A, xaB, xbB, m0B, m1B, 0.5f,
                 w1p, w2p, b1p, sB2, g, kh);
        m0A = m1A; m0B = m1B;
        xaA = xbA; xaB = xbB;
    }
    // all 4 lanes of the row hold identical z; lane slot q0 writes [2q0, 2q0+1]
    {
        float a0, a1, b0, b1v;
        unpack2(zA[q0], a0, a1);
        unpack2(zB[q0], b0, b1v);
        g_z[rowA * 8 + 2 * q0]     = a0;
        g_z[rowA * 8 + 2 * q0 + 1] = a1;
        g_z[rowB * 8 + 2 * q0]     = b0;
        g_z[rowB * 8 + 2 * q0 + 1] = b1v;
    }
}

// ---------------- k2: readout MLP with smem-cached Wr2 ----------------
#define K2_W2   0                    // 200*201 floats
#define K2_W1   (200 * 201)          // 1600
#define K2_B1   (K2_W1 + 1600)       // 200
#define K2_B2   (K2_B1 + 200)        // 200
#define K2_W3   (K2_B2 + 200)        // 200
#define K2_H1   (K2_W3 + 200)        // 8 warps * 1600
#define K2_SMEM_FLOATS (K2_H1 + 8 * 1600)
#define K2_SMEM_BYTES  (K2_SMEM_FLOATS * 4)

__global__ void __launch_bounds__(256, 1)
k2_readout(const float* __restrict__ Wr1, const float* __restrict__ br1,
           const float* __restrict__ Wr2, const float* __restrict__ br2,
           const float* __restrict__ Wr3, const float* __restrict__ br3) {
    extern __shared__ __align__(16) float sm[];
    int tid = threadIdx.x;
    int lane = tid & 31;
    int w = tid >> 5;

    for (int i = tid; i < 200 * 200; i += 256)
        sm[K2_W2 + (i / 200) * 201 + (i % 200)] = Wr2[i];
    for (int i = tid; i < 1600; i += 256) sm[K2_W1 + i] = Wr1[i];
    for (int i = tid; i < 200; i += 256) {
        sm[K2_B1 + i] = br1[i];
        sm[K2_B2 + i] = br2[i];
        sm[K2_W3 + i] = Wr3[i];
    }
    __syncthreads();

    float* h1w = sm + K2_H1 + w * 1600;
    float b3 = __ldg(br3);

    for (int pass = 0; pass < 2; pass++) {
        int row0 = blockIdx.x * 128 + w * 16 + pass * 8;

        float z8[8][8];
#pragma unroll
        for (int r = 0; r < 8; r++) {
            const float4* zp = reinterpret_cast<const float4*>(g_z + (row0 + r) * 8);
            float4 u = zp[0], v = zp[1];
            z8[r][0] = u.x; z8[r][1] = u.y; z8[r][2] = u.z; z8[r][3] = u.w;
            z8[r][4] = v.x; z8[r][5] = v.y; z8[r][6] = v.z; z8[r][7] = v.w;
        }
        for (int j = lane; j < 200; j += 32) {
            const float4* wp = reinterpret_cast<const float4*>(sm + K2_W1 + j * 8);
            float4 a = wp[0], b = wp[1];
            float bj = sm[K2_B1 + j];
#pragma unroll
            for (int r = 0; r < 8; r++) {
                float h = bj;
                h = fmaf(a.x, z8[r][0], h); h = fmaf(a.y, z8[r][1], h);
                h = fmaf(a.z, z8[r][2], h); h = fmaf(a.w, z8[r][3], h);
                h = fmaf(b.x, z8[r][4], h); h = fmaf(b.y, z8[r][5], h);
                h = fmaf(b.z, z8[r][6], h); h = fmaf(b.w, z8[r][7], h);
                h1w[j * 8 + r] = h * normcdff(h);
            }
        }
        __syncwarp();

        ull acc[7][4];
#pragma unroll
        for (int u = 0; u < 7; u++)
#pragma unroll
            for (int q = 0; q < 4; q++) acc[u][q] = 0ull;

        for (int q = 0; q < 200; q++) {
            const ull* hp = reinterpret_cast<const ull*>(h1w + q * 8);
            ull h01 = hp[0], h23 = hp[1], h45 = hp[2], h67 = hp[3];
#pragma unroll
            for (int u = 0; u < 7; u++) {
                int j = lane + 32 * u;
                float wv = (j < 200) ? sm[K2_W2 + j * 201 + q] : 0.f;
                ull w2 = pack2(wv, wv);
                acc[u][0] = fma2(w2, h01, acc[u][0]);
                acc[u][1] = fma2(w2, h23, acc[u][1]);
                acc[u][2] = fma2(w2, h45, acc[u][2]);
                acc[u][3] = fma2(w2, h67, acc[u][3]);
            }
        }

        float part[8];
#pragma unroll
        for (int r = 0; r < 8; r++) part[r] = 0.f;
#pragma unroll
        for (int u = 0; u < 7; u++) {
            int j = lane + 32 * u;
            if (j < 200) {
                float w3 = sm[K2_W3 + j];
                float b2j = sm[K2_B2 + j];
#pragma unroll
                for (int q = 0; q < 4; q++) {
                    float v0, v1; unpack2(acc[u][q], v0, v1);
                    v0 += b2j; v1 += b2j;
                    part[2 * q]     = fmaf(w3, v0 * normcdff(v0), part[2 * q]);
                    part[2 * q + 1] = fmaf(w3, v1 * normcdff(v1), part[2 * q + 1]);
                }
            }
        }
#pragma unroll
        for (int r = 0; r < 8; r++)
#pragma unroll
            for (int m = 16; m >= 1; m >>= 1)
                part[r] += __shfl_xor_sync(0xffffffffu, part[r], m);

        if (lane < 8) {
            float t = part[lane] + b3;
            float sg = 1.0f / (1.0f + expf(-t));
            g_T10[row0 + lane] = 0.1f + sg * (7.0f - 0.1f);
        }
        __syncwarp();
    }
}

__global__ void __launch_bounds__(128)
k3_out(const float* __restrict__ fa_in, const float* __restrict__ TR,
       const int* __restrict__ fa_len, float* __restrict__ out) {
    int lane = threadIdx.x & 31;
    int w = threadIdx.x >> 5;
    int row = blockIdx.x * 4 + w;

    float T10 = g_T10[row];
    float R1 = 1.0f / T10;
    float E = expf(-TR[row] * R1);
    float fa = fa_in[row * LL + lane];
    float xo = (1.0f - E) * sinf(fa) / (1.0f - cosf(fa) * E);

    float ssum = xo;
#pragma unroll
    for (int m = 16; m >= 1; m >>= 1) ssum += __shfl_xor_sync(0xffffffffu, ssum, m);

    float fl = (float)fa_len[row];
    out[row * LL + lane] = xo * fl / ssum;
    if (lane == 0) {
        out[BB * LL + row] = T10;       // T10
        out[BB * LL + BB + row] = 1.0f; // M0
    }
}

extern "C" void kernel_launch(void* const* d_in, const int* in_sizes, int n_in,
                              void* d_out, int out_size) {
    const float* X_fa_in    = (const float*)d_in[0];
    const float* fa_vals_in = (const float*)d_in[1];
    const float* TR_vals    = (const float*)d_in[2];
    const float* W_init     = (const float*)d_in[3];
    const float* b_init     = (const float*)d_in[4];
    const float* W1         = (const float*)d_in[5];
    const float* b1         = (const float*)d_in[6];
    const float* W2         = (const float*)d_in[7];
    const float* b2         = (const float*)d_in[8];
    const float* Wr1        = (const float*)d_in[9];
    const float* br1        = (const float*)d_in[10];
    const float* Wr2        = (const float*)d_in[11];
    const float* br2        = (const float*)d_in[12];
    const float* Wr3        = (const float*)d_in[13];
    const float* br3        = (const float*)d_in[14];
    // d_in[15] = fa_mask (unused)
    const int*   fa_len     = (const int*)d_in[16];

    float* out = (float*)d_out;

    // host-state op (not a stream op): capture-safe, deterministic, no alloc
    cudaFuncSetAttribute(k2_readout, cudaFuncAttributeMaxDynamicSharedMemorySize,
                         K2_SMEM_BYTES);

    k1_ode<<<BB / 16, 32>>>(X_fa_in, fa_vals_in, fa_len, W_init, b_init, W1, b1, W2, b2);
    k2_readout<<<128, 256, K2_SMEM_BYTES>>>(Wr1, br1, Wr2, br2, Wr3, br3);
    k3_out<<<BB / 4, 128>>>(fa_vals_in, TR_vals, fa_len, out);
}